// round 1
// baseline (speedup 1.0000x reference)
#include <cuda_runtime.h>
#include <cstdint>
#include <cstddef>

#define B_  2
#define T_  4096
#define C_  2048
#define NH  16
#define NKV 4
#define D_  128

// Scratch (allocation-free rule: __device__ globals)
__device__ float g_q[B_ * T_ * NH * D_];   // 64 MB  [B,T,H,D]
__device__ float g_k[B_ * T_ * NKV * D_];  // 16 MB  [B,T,KV,D]
__device__ float g_v[B_ * T_ * NKV * D_];  // 16 MB
__device__ float g_y[B_ * T_ * NH * D_];   // 64 MB  [B,T,H,D]

// ---------------------------------------------------------------------------
// TF32 helpers
// ---------------------------------------------------------------------------
__device__ __forceinline__ uint32_t f2tf32(float x) {
    uint32_t r;
    asm("cvt.rna.tf32.f32 %0, %1;" : "=r"(r) : "f"(x));
    return r;
}

__device__ __forceinline__ void mma_tf32(float* c, const uint32_t* a, const uint32_t* b) {
    asm volatile(
        "mma.sync.aligned.m16n8k8.row.col.f32.tf32.tf32.f32 "
        "{%0,%1,%2,%3}, {%4,%5,%6,%7}, {%8,%9}, {%0,%1,%2,%3};\n"
        : "+f"(c[0]), "+f"(c[1]), "+f"(c[2]), "+f"(c[3])
        : "r"(a[0]), "r"(a[1]), "r"(a[2]), "r"(a[3]),
          "r"(b[0]), "r"(b[1]));
}

// ---------------------------------------------------------------------------
// GEMM: C[M,N] = sum_k A[M,K] * Bw[N,K]   (A, Bw fp32 row-major, tf32 mma)
// Block tile 128x128, k-tile 32, 256 threads = 8 warps (2M x 4N), warp 64x32.
// All dims divisible (M=8192, N in {512,2048}, K=2048).
// ---------------------------------------------------------------------------
__global__ __launch_bounds__(256, 1) void gemm_tf32(
    const float* __restrict__ A, const float* __restrict__ Bw,
    float* __restrict__ C, int M, int N, int K)
{
    __shared__ float As[128][36];
    __shared__ float Bs[128][36];

    const int tid  = threadIdx.x;
    const int lane = tid & 31;
    const int warp = tid >> 5;
    const int g  = lane >> 2;   // 0..7
    const int tg = lane & 3;    // 0..3
    const int wm = warp & 1;    // 2 warps along M
    const int wn = warp >> 1;   // 4 warps along N
    const int bm = blockIdx.y << 7;
    const int bn = blockIdx.x << 7;

    const int lrow = tid >> 3;        // 0..31
    const int lcol = (tid & 7) << 2;  // 0..28 step 4

    float acc[4][4][4];
#pragma unroll
    for (int i = 0; i < 4; i++)
#pragma unroll
        for (int j = 0; j < 4; j++)
#pragma unroll
            for (int e = 0; e < 4; e++) acc[i][j][e] = 0.f;

    const float* Ab = A  + (size_t)bm * K + lcol;
    const float* Bb = Bw + (size_t)bn * K + lcol;

    float4 pa[4], pb[4];
#pragma unroll
    for (int r = 0; r < 4; r++) {
        pa[r] = *(const float4*)(Ab + (size_t)(lrow + (r << 5)) * K);
        pb[r] = *(const float4*)(Bb + (size_t)(lrow + (r << 5)) * K);
    }

    const int nkt = K >> 5;
    for (int kt = 0; kt < nkt; kt++) {
#pragma unroll
        for (int r = 0; r < 4; r++) {
            float* as = &As[lrow + (r << 5)][lcol];
            as[0] = __uint_as_float(f2tf32(pa[r].x));
            as[1] = __uint_as_float(f2tf32(pa[r].y));
            as[2] = __uint_as_float(f2tf32(pa[r].z));
            as[3] = __uint_as_float(f2tf32(pa[r].w));
            float* bs = &Bs[lrow + (r << 5)][lcol];
            bs[0] = __uint_as_float(f2tf32(pb[r].x));
            bs[1] = __uint_as_float(f2tf32(pb[r].y));
            bs[2] = __uint_as_float(f2tf32(pb[r].z));
            bs[3] = __uint_as_float(f2tf32(pb[r].w));
        }
        __syncthreads();

        if (kt + 1 < nkt) {
            const float* Ab2 = Ab + ((kt + 1) << 5);
            const float* Bb2 = Bb + ((kt + 1) << 5);
#pragma unroll
            for (int r = 0; r < 4; r++) {
                pa[r] = *(const float4*)(Ab2 + (size_t)(lrow + (r << 5)) * K);
                pb[r] = *(const float4*)(Bb2 + (size_t)(lrow + (r << 5)) * K);
            }
        }

#pragma unroll
        for (int ks = 0; ks < 4; ks++) {
            uint32_t af[4][4];
            uint32_t bf[4][2];
            const int cc = (ks << 3) + tg;
#pragma unroll
            for (int mt = 0; mt < 4; mt++) {
                const int r0 = (wm << 6) + (mt << 4) + g;
                af[mt][0] = __float_as_uint(As[r0][cc]);
                af[mt][1] = __float_as_uint(As[r0 + 8][cc]);
                af[mt][2] = __float_as_uint(As[r0][cc + 4]);
                af[mt][3] = __float_as_uint(As[r0 + 8][cc + 4]);
            }
#pragma unroll
            for (int nt = 0; nt < 4; nt++) {
                const int r0 = (wn << 5) + (nt << 3) + g;
                bf[nt][0] = __float_as_uint(Bs[r0][cc]);
                bf[nt][1] = __float_as_uint(Bs[r0][cc + 4]);
            }
#pragma unroll
            for (int mt = 0; mt < 4; mt++)
#pragma unroll
                for (int nt = 0; nt < 4; nt++)
                    mma_tf32(acc[mt][nt], af[mt], bf[nt]);
        }
        __syncthreads();
    }

#pragma unroll
    for (int mt = 0; mt < 4; mt++) {
#pragma unroll
        for (int nt = 0; nt < 4; nt++) {
            const int row = bm + (wm << 6) + (mt << 4) + g;
            const int col = bn + (wn << 5) + (nt << 3) + (tg << 1);
            *(float2*)(C + (size_t)row * N + col) =
                make_float2(acc[mt][nt][0], acc[mt][nt][1]);
            *(float2*)(C + (size_t)(row + 8) * N + col) =
                make_float2(acc[mt][nt][2], acc[mt][nt][3]);
        }
    }
}

// ---------------------------------------------------------------------------
// RoPE in-place. x: [B*T, H, 128]. cache: [T, 64, 2] (cos, sin).
// One thread per (bt, h, pair).
// ---------------------------------------------------------------------------
__global__ void rope_kernel(float* __restrict__ x, const float* __restrict__ cache,
                            int H, int npairs)
{
    int p = blockIdx.x * blockDim.x + threadIdx.x;
    if (p >= npairs) return;
    int i  = p & 63;
    int ph = p >> 6;
    int hh = ph % H;
    int bt = ph / H;
    int t  = bt & (T_ - 1);

    float* xp = x + ((size_t)bt * H + hh) * D_ + (i << 1);
    float2 xv = *(float2*)xp;
    float2 cs = *(const float2*)(cache + ((size_t)t * 64 + i) * 2);
    float2 o;
    o.x = xv.x * cs.x - xv.y * cs.y;
    o.y = xv.x * cs.y + xv.y * cs.x;
    *(float2*)xp = o;
}

// ---------------------------------------------------------------------------
// Sliding-window attention (window 256, dilation 1), GQA 16:4.
// Block = one (b, head, 128-query chunk). 256 threads: 2 threads per query,
// thread owns d-parity `half` (64 elements). Keys iterated in 32-key smem
// tiles spanning [c0-256, c0+128). Single-pass softmax (no max subtraction:
// scores are O(1) here; exp cannot overflow), masked keys contribute 0.
// Smem K/V stored parity-permuted with half1 shifted +68 words so both
// halves read conflict-free LDS.128.
// ---------------------------------------------------------------------------
__global__ __launch_bounds__(256, 1) void attn_kernel(
    const float* __restrict__ Q, const float* __restrict__ K,
    const float* __restrict__ V, float* __restrict__ Y)
{
    __shared__ float Ks[32][136];
    __shared__ float Vs[32][136];

    const int tid  = threadIdx.x;
    const int qi   = tid >> 1;
    const int half = tid & 1;
    const int b    = blockIdx.z;
    const int h    = blockIdx.y;
    const int c0   = blockIdx.x << 7;
    const int t    = c0 + qi;
    const int kvh  = h >> 2;
    const int hoff = half * 68;

    float qreg[64];
    {
        const float* qp = Q + ((size_t)(b * T_ + t) * NH + h) * D_ + half;
        const float scale = 0.088388347648318447f;  // 1/sqrt(128)
#pragma unroll
        for (int i = 0; i < 64; i++) qreg[i] = qp[2 * i] * scale;
    }
    float acc[64];
#pragma unroll
    for (int i = 0; i < 64; i++) acc[i] = 0.f;
    float l = 0.f;

    const int warp = tid >> 5;
    const int wq0  = c0 + (warp << 4);   // min query t in this warp
    const int wq1  = wq0 + 15;           // max query t in this warp

    const int ldrow = tid >> 5;   // 0..7
    const int ldc   = tid & 31;   // float4 index within 128-float row

    for (int tile = 0; tile < 12; tile++) {
        const int kbase = c0 - 256 + (tile << 5);
        __syncthreads();
#pragma unroll
        for (int r = 0; r < 4; r++) {
            const int row = ldrow + (r << 3);
            const int kp  = kbase + row;
            float4 kk = make_float4(0.f, 0.f, 0.f, 0.f);
            float4 vv = make_float4(0.f, 0.f, 0.f, 0.f);
            if (kp >= 0) {
                const size_t base =
                    ((size_t)(b * T_ + kp) * NKV + kvh) * D_ + ((size_t)ldc << 2);
                kk = *(const float4*)(K + base);
                vv = *(const float4*)(V + base);
            }
            const int c2 = ldc << 1;
            *(float2*)&Ks[row][c2]      = make_float2(kk.x, kk.z);  // even d
            *(float2*)&Ks[row][68 + c2] = make_float2(kk.y, kk.w);  // odd d
            *(float2*)&Vs[row][c2]      = make_float2(vv.x, vv.z);
            *(float2*)&Vs[row][68 + c2] = make_float2(vv.y, vv.w);
        }
        __syncthreads();

        // warp-uniform skip: no key in this tile can be valid for any query here
        if (kbase > wq1 || kbase + 31 < wq0 - 255) continue;

#pragma unroll 1
        for (int jj = 0; jj < 32; jj++) {
            const int kp = kbase + jj;
            float s0 = 0.f, s1 = 0.f, s2 = 0.f, s3 = 0.f;
            const float* kr = &Ks[jj][hoff];
#pragma unroll
            for (int i4 = 0; i4 < 16; i4++) {
                float4 kk = *(const float4*)(kr + (i4 << 2));
                s0 = fmaf(qreg[i4 * 4 + 0], kk.x, s0);
                s1 = fmaf(qreg[i4 * 4 + 1], kk.y, s1);
                s2 = fmaf(qreg[i4 * 4 + 2], kk.z, s2);
                s3 = fmaf(qreg[i4 * 4 + 3], kk.w, s3);
            }
            float s = (s0 + s1) + (s2 + s3);
            s += __shfl_xor_sync(0xffffffffu, s, 1);
            if (kp >= 0 && kp <= t && kp >= t - 255) {
                const float p = __expf(s);
                l += p;
                const float* vr = &Vs[jj][hoff];
#pragma unroll
                for (int i4 = 0; i4 < 16; i4++) {
                    float4 vv = *(const float4*)(vr + (i4 << 2));
                    acc[i4 * 4 + 0] = fmaf(p, vv.x, acc[i4 * 4 + 0]);
                    acc[i4 * 4 + 1] = fmaf(p, vv.y, acc[i4 * 4 + 1]);
                    acc[i4 * 4 + 2] = fmaf(p, vv.z, acc[i4 * 4 + 2]);
                    acc[i4 * 4 + 3] = fmaf(p, vv.w, acc[i4 * 4 + 3]);
                }
            }
        }
    }

    const float rl = 1.0f / l;  // l >= exp(self-score) > 0 always
    float* yp = Y + ((size_t)(b * T_ + t) * NH + h) * D_ + half;
#pragma unroll
    for (int i = 0; i < 64; i++) yp[2 * i] = acc[i] * rl;
}

// ---------------------------------------------------------------------------
// Launch. Inputs (metadata order): x, wq, wk, wv, wo, rope_cache. Out: fp32.
// ---------------------------------------------------------------------------
extern "C" void kernel_launch(void* const* d_in, const int* in_sizes, int n_in,
                              void* d_out, int out_size)
{
    const float* x    = (const float*)d_in[0];
    const float* wq   = (const float*)d_in[1];
    const float* wk   = (const float*)d_in[2];
    const float* wv   = (const float*)d_in[3];
    const float* wo   = (const float*)d_in[4];
    const float* rope = (const float*)d_in[5];
    float* out = (float*)d_out;

    float *pq, *pk, *pv, *py;
    cudaGetSymbolAddress((void**)&pq, g_q);
    cudaGetSymbolAddress((void**)&pk, g_k);
    cudaGetSymbolAddress((void**)&pv, g_v);
    cudaGetSymbolAddress((void**)&py, g_y);

    const int M = B_ * T_;  // 8192
    dim3 blk(256);

    // QKV projections (q[m][h*128+d] = sum_k x[m][k] * wq[h*128+d][k])
    gemm_tf32<<<dim3((NH  * D_) / 128, M / 128), blk>>>(x, wq, pq, M, NH  * D_, C_);
    gemm_tf32<<<dim3((NKV * D_) / 128, M / 128), blk>>>(x, wk, pk, M, NKV * D_, C_);
    gemm_tf32<<<dim3((NKV * D_) / 128, M / 128), blk>>>(x, wv, pv, M, NKV * D_, C_);

    // RoPE on q and k
    const int nq = M * NH * 64;
    rope_kernel<<<(nq + 255) / 256, 256>>>(pq, rope, NH, nq);
    const int nk = M * NKV * 64;
    rope_kernel<<<(nk + 255) / 256, 256>>>(pk, rope, NKV, nk);

    // Sliding-window attention -> y [B,T,H,D]
    attn_kernel<<<dim3(T_ / 128, NH, B_), 256>>>(pq, pk, pv, py);

    // Output projection: out[m][c] = sum_hd y[m][hd] * wo[c][hd]
    gemm_tf32<<<dim3(C_ / 128, M / 128), blk>>>(py, wo, out, M, C_, C_);
}

// round 3
// speedup vs baseline: 1.0573x; 1.0573x over previous
#include <cuda_runtime.h>
#include <cstdint>
#include <cstddef>

#define B_  2
#define T_  4096
#define C_  2048
#define NH  16
#define NKV 4
#define D_  128

// Scratch (allocation-free rule: __device__ globals)
__device__ __align__(256) float g_q[B_ * T_ * NH * D_];   // [B,T,H,D]
__device__ __align__(256) float g_k[B_ * T_ * NKV * D_];
__device__ __align__(256) float g_v[B_ * T_ * NKV * D_];
__device__ __align__(256) float g_y[B_ * T_ * NH * D_];
__device__ __align__(256) float g_x[B_ * T_ * C_];        // tf32-rounded inputs
__device__ __align__(256) float g_wq[NH * D_ * C_];
__device__ __align__(256) float g_wk[NKV * D_ * C_];
__device__ __align__(256) float g_wv[NKV * D_ * C_];
__device__ __align__(256) float g_wo[C_ * C_];

// ---------------------------------------------------------------------------
// Helpers (arch-agnostic PTX only: sm_80-level mma/cp.async — NO tcgen05,
// the GPU-side build targets plain sm_103 which rejects sm_103a features)
// ---------------------------------------------------------------------------
__device__ __forceinline__ uint32_t smem_u32(const void* p) {
    uint32_t a;
    asm("{ .reg .u64 t; cvta.to.shared.u64 t, %1; cvt.u32.u64 %0, t; }"
        : "=r"(a) : "l"(p));
    return a;
}

__device__ __forceinline__ uint32_t f2tf32(float x) {
    uint32_t r;
    asm("cvt.rna.tf32.f32 %0, %1;" : "=r"(r) : "f"(x));
    return r;
}

__device__ __forceinline__ void cp16(uint32_t dst, const void* src) {
    asm volatile("cp.async.cg.shared.global [%0], [%1], 16;\n"
                 :: "r"(dst), "l"(src));
}
#define CP_COMMIT() asm volatile("cp.async.commit_group;" ::: "memory")
#define CP_WAIT1()  asm volatile("cp.async.wait_group 1;" ::: "memory")

__device__ __forceinline__ void mma_tf32(float* c, const uint32_t* a, const uint32_t* b) {
    asm volatile(
        "mma.sync.aligned.m16n8k8.row.col.f32.tf32.tf32.f32 "
        "{%0,%1,%2,%3}, {%4,%5,%6,%7}, {%8,%9}, {%0,%1,%2,%3};\n"
        : "+f"(c[0]), "+f"(c[1]), "+f"(c[2]), "+f"(c[3])
        : "r"(a[0]), "r"(a[1]), "r"(a[2]), "r"(a[3]),
          "r"(b[0]), "r"(b[1]));
}

// ---------------------------------------------------------------------------
// GEMM v2: C[M,N] = A[M,K] * Bw[N,K]^T. A, Bw pre-rounded to tf32 bit patterns.
// Block 128(M) x 256(N), k-tile 32, 8 warps (2M x 4N), warp tile 64x64.
// cp.async double-buffered; fragment smem pad 36 floats -> conflict-free.
// Requires M%128==0, N%256==0, K%32==0.
// ---------------------------------------------------------------------------
#define GPAD 36
#define A_STAGE_B (128 * GPAD * 4)          // 18432
#define B_STAGE_B (256 * GPAD * 4)          // 36864
#define GM_SMEM   (2 * (A_STAGE_B + B_STAGE_B))  // 110592

__global__ __launch_bounds__(256, 1) void gemm_v2(
    const float* __restrict__ A, const float* __restrict__ Bw,
    float* __restrict__ C, int M, int N, int K)
{
    extern __shared__ __align__(128) char smem[];
    const uint32_t sbase = smem_u32(smem);
    const uint32_t aoff[2] = { 0u, (uint32_t)A_STAGE_B };
    const uint32_t boff[2] = { 2u * A_STAGE_B, 2u * A_STAGE_B + B_STAGE_B };

    const int tid  = threadIdx.x;
    const int lane = tid & 31;
    const int warp = tid >> 5;
    const int g    = lane >> 2;   // 0..7
    const int tg   = lane & 3;    // 0..3
    const int wm   = warp & 1;    // 2 warps along M
    const int wn   = warp >> 1;   // 4 warps along N
    const int bm   = blockIdx.y << 7;
    const int bn   = blockIdx.x << 8;

    const int arow = tid >> 3;          // 0..31  (x4 -> 128 rows)
    const int aseg = (tid & 7) << 4;    // byte seg 0..112

    float acc[4][8][4];
#pragma unroll
    for (int i = 0; i < 4; i++)
#pragma unroll
        for (int j = 0; j < 8; j++)
#pragma unroll
            for (int e = 0; e < 4; e++) acc[i][j][e] = 0.f;

    const float* Ag = A  + (size_t)bm * K;
    const float* Bg = Bw + (size_t)bn * K;

    auto load_stage = [&](int sp, int kt) {
        const float* As = Ag + (kt << 5);
        const float* Bs = Bg + (kt << 5);
        const uint32_t ab = sbase + aoff[sp];
        const uint32_t bb = sbase + boff[sp];
#pragma unroll
        for (int i = 0; i < 4; i++) {
            int row = arow + (i << 5);
            cp16(ab + row * (GPAD * 4) + aseg, As + (size_t)row * K + (aseg >> 2));
        }
#pragma unroll
        for (int i = 0; i < 8; i++) {
            int row = arow + (i << 5);
            cp16(bb + row * (GPAD * 4) + aseg, Bs + (size_t)row * K + (aseg >> 2));
        }
    };

    const int nkt = K >> 5;
    load_stage(0, 0); CP_COMMIT();
    load_stage(1, 1); CP_COMMIT();

    for (int kt = 0; kt < nkt; kt++) {
        CP_WAIT1();
        __syncthreads();
        const int s = kt & 1;
        const float* Asm = (const float*)(smem + aoff[s]);
        const float* Bsm = (const float*)(smem + boff[s]);

#pragma unroll
        for (int ks = 0; ks < 4; ks++) {
            const int cc = (ks << 3) + tg;
            uint32_t af[4][4];
            uint32_t bf[8][2];
#pragma unroll
            for (int mt = 0; mt < 4; mt++) {
                const int r0 = (wm << 6) + (mt << 4) + g;
                af[mt][0] = __float_as_uint(Asm[r0 * GPAD + cc]);
                af[mt][1] = __float_as_uint(Asm[(r0 + 8) * GPAD + cc]);
                af[mt][2] = __float_as_uint(Asm[r0 * GPAD + cc + 4]);
                af[mt][3] = __float_as_uint(Asm[(r0 + 8) * GPAD + cc + 4]);
            }
#pragma unroll
            for (int nt = 0; nt < 8; nt++) {
                const int r0 = (wn << 6) + (nt << 3) + g;
                bf[nt][0] = __float_as_uint(Bsm[r0 * GPAD + cc]);
                bf[nt][1] = __float_as_uint(Bsm[r0 * GPAD + cc + 4]);
            }
#pragma unroll
            for (int mt = 0; mt < 4; mt++)
#pragma unroll
                for (int nt = 0; nt < 8; nt++)
                    mma_tf32(acc[mt][nt], af[mt], bf[nt]);
        }
        __syncthreads();
        if (kt + 2 < nkt) load_stage(s, kt + 2);
        CP_COMMIT();
    }

    // Epilogue: direct float2 stores.
#pragma unroll
    for (int mt = 0; mt < 4; mt++) {
#pragma unroll
        for (int nt = 0; nt < 8; nt++) {
            const int row = bm + (wm << 6) + (mt << 4) + g;
            const int col = bn + (wn << 6) + (nt << 3) + (tg << 1);
            *(float2*)(C + (size_t)row * N + col) =
                make_float2(acc[mt][nt][0], acc[mt][nt][1]);
            *(float2*)(C + (size_t)(row + 8) * N + col) =
                make_float2(acc[mt][nt][2], acc[mt][nt][3]);
        }
    }
}

// ---------------------------------------------------------------------------
// Elementwise tf32 (RNA) rounding pass: dst = round_tf32(src)
// ---------------------------------------------------------------------------
__global__ void round_tf32_kernel(float* __restrict__ dst,
                                  const float* __restrict__ src, int n4)
{
    int i = blockIdx.x * blockDim.x + threadIdx.x;
    if (i >= n4) return;
    float4 v = ((const float4*)src)[i];
    v.x = __uint_as_float(f2tf32(v.x));
    v.y = __uint_as_float(f2tf32(v.y));
    v.z = __uint_as_float(f2tf32(v.z));
    v.w = __uint_as_float(f2tf32(v.w));
    ((float4*)dst)[i] = v;
}

// ---------------------------------------------------------------------------
// RoPE in-place. x: [B*T, H, 128]. cache: [T, 64, 2] (cos, sin).
// ---------------------------------------------------------------------------
__global__ void rope_kernel(float* __restrict__ x, const float* __restrict__ cache,
                            int H, int npairs)
{
    int p = blockIdx.x * blockDim.x + threadIdx.x;
    if (p >= npairs) return;
    int i  = p & 63;
    int ph = p >> 6;
    int hh = ph % H;
    int bt = ph / H;
    int t  = bt & (T_ - 1);

    float* xp = x + ((size_t)bt * H + hh) * D_ + (i << 1);
    float2 xv = *(float2*)xp;
    float2 cs = *(const float2*)(cache + ((size_t)t * 64 + i) * 2);
    float2 o;
    o.x = xv.x * cs.x - xv.y * cs.y;
    o.y = xv.x * cs.y + xv.y * cs.x;
    *(float2*)xp = o;
}

// ---------------------------------------------------------------------------
// Sliding-window attention (window 256, dilation 1), GQA 16:4.
// Output is tf32-rounded (feeds the tf32 output projection).
// ---------------------------------------------------------------------------
__global__ __launch_bounds__(256, 1) void attn_kernel(
    const float* __restrict__ Q, const float* __restrict__ K,
    const float* __restrict__ V, float* __restrict__ Y)
{
    __shared__ float Ks[32][136];
    __shared__ float Vs[32][136];

    const int tid  = threadIdx.x;
    const int qi   = tid >> 1;
    const int half = tid & 1;
    const int b    = blockIdx.z;
    const int h    = blockIdx.y;
    const int c0   = blockIdx.x << 7;
    const int t    = c0 + qi;
    const int kvh  = h >> 2;
    const int hoff = half * 68;

    float qreg[64];
    {
        const float* qp = Q + ((size_t)(b * T_ + t) * NH + h) * D_ + half;
        const float scale = 0.088388347648318447f;  // 1/sqrt(128)
#pragma unroll
        for (int i = 0; i < 64; i++) qreg[i] = qp[2 * i] * scale;
    }
    float acc[64];
#pragma unroll
    for (int i = 0; i < 64; i++) acc[i] = 0.f;
    float l = 0.f;

    const int warp = tid >> 5;
    const int wq0  = c0 + (warp << 4);
    const int wq1  = wq0 + 15;

    const int ldrow = tid >> 5;
    const int ldc   = tid & 31;

    for (int tile = 0; tile < 12; tile++) {
        const int kbase = c0 - 256 + (tile << 5);
        __syncthreads();
#pragma unroll
        for (int r = 0; r < 4; r++) {
            const int row = ldrow + (r << 3);
            const int kp  = kbase + row;
            float4 kk = make_float4(0.f, 0.f, 0.f, 0.f);
            float4 vv = make_float4(0.f, 0.f, 0.f, 0.f);
            if (kp >= 0) {
                const size_t base =
                    ((size_t)(b * T_ + kp) * NKV + kvh) * D_ + ((size_t)ldc << 2);
                kk = *(const float4*)(K + base);
                vv = *(const float4*)(V + base);
            }
            const int c2 = ldc << 1;
            *(float2*)&Ks[row][c2]      = make_float2(kk.x, kk.z);
            *(float2*)&Ks[row][68 + c2] = make_float2(kk.y, kk.w);
            *(float2*)&Vs[row][c2]      = make_float2(vv.x, vv.z);
            *(float2*)&Vs[row][68 + c2] = make_float2(vv.y, vv.w);
        }
        __syncthreads();

        if (kbase > wq1 || kbase + 31 < wq0 - 255) continue;

#pragma unroll 1
        for (int jj = 0; jj < 32; jj++) {
            const int kp = kbase + jj;
            float s0 = 0.f, s1 = 0.f, s2 = 0.f, s3 = 0.f;
            const float* kr = &Ks[jj][hoff];
#pragma unroll
            for (int i4 = 0; i4 < 16; i4++) {
                float4 kk = *(const float4*)(kr + (i4 << 2));
                s0 = fmaf(qreg[i4 * 4 + 0], kk.x, s0);
                s1 = fmaf(qreg[i4 * 4 + 1], kk.y, s1);
                s2 = fmaf(qreg[i4 * 4 + 2], kk.z, s2);
                s3 = fmaf(qreg[i4 * 4 + 3], kk.w, s3);
            }
            float s = (s0 + s1) + (s2 + s3);
            s += __shfl_xor_sync(0xffffffffu, s, 1);
            if (kp >= 0 && kp <= t && kp >= t - 255) {
                const float p = __expf(s);
                l += p;
                const float* vr = &Vs[jj][hoff];
#pragma unroll
                for (int i4 = 0; i4 < 16; i4++) {
                    float4 vv = *(const float4*)(vr + (i4 << 2));
                    acc[i4 * 4 + 0] = fmaf(p, vv.x, acc[i4 * 4 + 0]);
                    acc[i4 * 4 + 1] = fmaf(p, vv.y, acc[i4 * 4 + 1]);
                    acc[i4 * 4 + 2] = fmaf(p, vv.z, acc[i4 * 4 + 2]);
                    acc[i4 * 4 + 3] = fmaf(p, vv.w, acc[i4 * 4 + 3]);
                }
            }
        }
    }

    const float rl = 1.0f / l;
    float* yp = Y + ((size_t)(b * T_ + t) * NH + h) * D_ + half;
#pragma unroll
    for (int i = 0; i < 64; i++)
        yp[2 * i] = __uint_as_float(f2tf32(acc[i] * rl));
}

// ---------------------------------------------------------------------------
// Launch. Inputs (metadata order): x, wq, wk, wv, wo, rope_cache. Out: fp32.
// ---------------------------------------------------------------------------
extern "C" void kernel_launch(void* const* d_in, const int* in_sizes, int n_in,
                              void* d_out, int out_size)
{
    const float* x    = (const float*)d_in[0];
    const float* wq   = (const float*)d_in[1];
    const float* wk   = (const float*)d_in[2];
    const float* wv   = (const float*)d_in[3];
    const float* wo   = (const float*)d_in[4];
    const float* rope = (const float*)d_in[5];
    float* out = (float*)d_out;

    float *pq, *pk, *pv, *py, *px, *pwq, *pwk, *pwv, *pwo;
    cudaGetSymbolAddress((void**)&pq,  g_q);
    cudaGetSymbolAddress((void**)&pk,  g_k);
    cudaGetSymbolAddress((void**)&pv,  g_v);
    cudaGetSymbolAddress((void**)&py,  g_y);
    cudaGetSymbolAddress((void**)&px,  g_x);
    cudaGetSymbolAddress((void**)&pwq, g_wq);
    cudaGetSymbolAddress((void**)&pwk, g_wk);
    cudaGetSymbolAddress((void**)&pwv, g_wv);
    cudaGetSymbolAddress((void**)&pwo, g_wo);

    cudaFuncSetAttribute(gemm_v2, cudaFuncAttributeMaxDynamicSharedMemorySize, GM_SMEM);

    const int M = B_ * T_;  // 8192

    // tf32-round GEMM inputs once; GEMM then cp.asyncs raw bits.
    auto roundp = [&](float* dst, const float* src, int n) {
        int n4 = n / 4;
        round_tf32_kernel<<<(n4 + 255) / 256, 256>>>(dst, src, n4);
    };
    roundp(px,  x,  B_ * T_ * C_);
    roundp(pwq, wq, NH * D_ * C_);
    roundp(pwk, wk, NKV * D_ * C_);
    roundp(pwv, wv, NKV * D_ * C_);
    roundp(pwo, wo, C_ * C_);

    // QKV projections
    gemm_v2<<<dim3((NH  * D_) / 256, M / 128), 256, GM_SMEM>>>(px, pwq, pq, M, NH  * D_, C_);
    gemm_v2<<<dim3((NKV * D_) / 256, M / 128), 256, GM_SMEM>>>(px, pwk, pk, M, NKV * D_, C_);
    gemm_v2<<<dim3((NKV * D_) / 256, M / 128), 256, GM_SMEM>>>(px, pwv, pv, M, NKV * D_, C_);

    // RoPE on q and k
    const int nq = M * NH * 64;
    rope_kernel<<<(nq + 255) / 256, 256>>>(pq, rope, NH, nq);
    const int nk = M * NKV * 64;
    rope_kernel<<<(nk + 255) / 256, 256>>>(pk, rope, NKV, nk);

    // Sliding-window attention -> y (tf32-rounded)
    attn_kernel<<<dim3(T_ / 128, NH, B_), 256>>>(pq, pk, pv, py);

    // Output projection
    gemm_v2<<<dim3(C_ / 256, M / 128), 256, GM_SMEM>>>(py, pwo, out, M, C_, C_);
}

// round 4
// speedup vs baseline: 1.5348x; 1.4515x over previous
#include <cuda_runtime.h>
#include <cstdint>
#include <cstddef>

#define B_  2
#define T_  4096
#define C_  2048
#define NH  16
#define NKV 4
#define D_  128

// Scratch (allocation-free rule: __device__ globals)
__device__ __align__(256) float g_q[B_ * T_ * NH * D_];   // [B,T,H,D]
__device__ __align__(256) float g_k[B_ * T_ * NKV * D_];
__device__ __align__(256) float g_v[B_ * T_ * NKV * D_];
__device__ __align__(256) float g_y[B_ * T_ * NH * D_];
__device__ __align__(256) float g_x[B_ * T_ * C_];        // tf32-rounded inputs
__device__ __align__(256) float g_wq[NH * D_ * C_];
__device__ __align__(256) float g_wk[NKV * D_ * C_];
__device__ __align__(256) float g_wv[NKV * D_ * C_];
__device__ __align__(256) float g_wo[C_ * C_];

// ---------------------------------------------------------------------------
// Helpers (arch-agnostic PTX only — GPU-side build targets plain sm_103,
// which rejects all sm_103a-only features like tcgen05)
// ---------------------------------------------------------------------------
__device__ __forceinline__ uint32_t smem_u32(const void* p) {
    uint32_t a;
    asm("{ .reg .u64 t; cvta.to.shared.u64 t, %1; cvt.u32.u64 %0, t; }"
        : "=r"(a) : "l"(p));
    return a;
}

__device__ __forceinline__ uint32_t f2tf32(float x) {
    uint32_t r;
    asm("cvt.rna.tf32.f32 %0, %1;" : "=r"(r) : "f"(x));
    return r;
}

__device__ __forceinline__ void cp16(uint32_t dst, const void* src) {
    asm volatile("cp.async.cg.shared.global [%0], [%1], 16;\n"
                 :: "r"(dst), "l"(src));
}
#define CP_COMMIT() asm volatile("cp.async.commit_group;" ::: "memory")
#define CP_WAIT1()  asm volatile("cp.async.wait_group 1;" ::: "memory")
#define CP_WAIT0()  asm volatile("cp.async.wait_group 0;" ::: "memory")

__device__ __forceinline__ void mma_tf32(float* c, const uint32_t* a, const uint32_t* b) {
    asm volatile(
        "mma.sync.aligned.m16n8k8.row.col.f32.tf32.tf32.f32 "
        "{%0,%1,%2,%3}, {%4,%5,%6,%7}, {%8,%9}, {%0,%1,%2,%3};\n"
        : "+f"(c[0]), "+f"(c[1]), "+f"(c[2]), "+f"(c[3])
        : "r"(a[0]), "r"(a[1]), "r"(a[2]), "r"(a[3]),
          "r"(b[0]), "r"(b[1]));
}

// ---------------------------------------------------------------------------
// GEMM v2: C[M,N] = A[M,K] * Bw[N,K]^T. A, Bw pre-rounded to tf32 bit patterns.
// Block 128(M) x 256(N), k-tile 32, 8 warps (2M x 4N), warp tile 64x64.
// roundOut!=0 -> epilogue emits tf32-rounded values.
// ---------------------------------------------------------------------------
#define GPAD 36
#define A_STAGE_B (128 * GPAD * 4)
#define B_STAGE_B (256 * GPAD * 4)
#define GM_SMEM   (2 * (A_STAGE_B + B_STAGE_B))

__global__ __launch_bounds__(256, 1) void gemm_v2(
    const float* __restrict__ A, const float* __restrict__ Bw,
    float* __restrict__ C, int M, int N, int K, int roundOut)
{
    extern __shared__ __align__(128) char smem[];
    const uint32_t sbase = smem_u32(smem);
    const uint32_t aoff[2] = { 0u, (uint32_t)A_STAGE_B };
    const uint32_t boff[2] = { 2u * A_STAGE_B, 2u * A_STAGE_B + B_STAGE_B };

    const int tid  = threadIdx.x;
    const int lane = tid & 31;
    const int warp = tid >> 5;
    const int g    = lane >> 2;
    const int tg   = lane & 3;
    const int wm   = warp & 1;
    const int wn   = warp >> 1;
    const int bm   = blockIdx.y << 7;
    const int bn   = blockIdx.x << 8;

    const int arow = tid >> 3;
    const int aseg = (tid & 7) << 4;

    float acc[4][8][4];
#pragma unroll
    for (int i = 0; i < 4; i++)
#pragma unroll
        for (int j = 0; j < 8; j++)
#pragma unroll
            for (int e = 0; e < 4; e++) acc[i][j][e] = 0.f;

    const float* Ag = A  + (size_t)bm * K;
    const float* Bg = Bw + (size_t)bn * K;

    auto load_stage = [&](int sp, int kt) {
        const float* As = Ag + (kt << 5);
        const float* Bs = Bg + (kt << 5);
        const uint32_t ab = sbase + aoff[sp];
        const uint32_t bb = sbase + boff[sp];
#pragma unroll
        for (int i = 0; i < 4; i++) {
            int row = arow + (i << 5);
            cp16(ab + row * (GPAD * 4) + aseg, As + (size_t)row * K + (aseg >> 2));
        }
#pragma unroll
        for (int i = 0; i < 8; i++) {
            int row = arow + (i << 5);
            cp16(bb + row * (GPAD * 4) + aseg, Bs + (size_t)row * K + (aseg >> 2));
        }
    };

    const int nkt = K >> 5;
    load_stage(0, 0); CP_COMMIT();
    load_stage(1, 1); CP_COMMIT();

    for (int kt = 0; kt < nkt; kt++) {
        CP_WAIT1();
        __syncthreads();
        const int s = kt & 1;
        const float* Asm = (const float*)(smem + aoff[s]);
        const float* Bsm = (const float*)(smem + boff[s]);

#pragma unroll
        for (int ks = 0; ks < 4; ks++) {
            const int cc = (ks << 3) + tg;
            uint32_t af[4][4];
            uint32_t bf[8][2];
#pragma unroll
            for (int mt = 0; mt < 4; mt++) {
                const int r0 = (wm << 6) + (mt << 4) + g;
                af[mt][0] = __float_as_uint(Asm[r0 * GPAD + cc]);
                af[mt][1] = __float_as_uint(Asm[(r0 + 8) * GPAD + cc]);
                af[mt][2] = __float_as_uint(Asm[r0 * GPAD + cc + 4]);
                af[mt][3] = __float_as_uint(Asm[(r0 + 8) * GPAD + cc + 4]);
            }
#pragma unroll
            for (int nt = 0; nt < 8; nt++) {
                const int r0 = (wn << 6) + (nt << 3) + g;
                bf[nt][0] = __float_as_uint(Bsm[r0 * GPAD + cc]);
                bf[nt][1] = __float_as_uint(Bsm[r0 * GPAD + cc + 4]);
            }
#pragma unroll
            for (int mt = 0; mt < 4; mt++)
#pragma unroll
                for (int nt = 0; nt < 8; nt++)
                    mma_tf32(acc[mt][nt], af[mt], bf[nt]);
        }
        __syncthreads();
        if (kt + 2 < nkt) load_stage(s, kt + 2);
        CP_COMMIT();
    }

#pragma unroll
    for (int mt = 0; mt < 4; mt++) {
#pragma unroll
        for (int nt = 0; nt < 8; nt++) {
            float v0 = acc[mt][nt][0], v1 = acc[mt][nt][1];
            float v2 = acc[mt][nt][2], v3 = acc[mt][nt][3];
            if (roundOut) {
                v0 = __uint_as_float(f2tf32(v0));
                v1 = __uint_as_float(f2tf32(v1));
                v2 = __uint_as_float(f2tf32(v2));
                v3 = __uint_as_float(f2tf32(v3));
            }
            const int row = bm + (wm << 6) + (mt << 4) + g;
            const int col = bn + (wn << 6) + (nt << 3) + (tg << 1);
            *(float2*)(C + (size_t)row * N + col) = make_float2(v0, v1);
            *(float2*)(C + (size_t)(row + 8) * N + col) = make_float2(v2, v3);
        }
    }
}

// ---------------------------------------------------------------------------
// Elementwise tf32 (RNA) rounding pass: dst = round_tf32(src)
// ---------------------------------------------------------------------------
__global__ void round_tf32_kernel(float* __restrict__ dst,
                                  const float* __restrict__ src, int n4)
{
    int i = blockIdx.x * blockDim.x + threadIdx.x;
    if (i >= n4) return;
    float4 v = ((const float4*)src)[i];
    v.x = __uint_as_float(f2tf32(v.x));
    v.y = __uint_as_float(f2tf32(v.y));
    v.z = __uint_as_float(f2tf32(v.z));
    v.w = __uint_as_float(f2tf32(v.w));
    ((float4*)dst)[i] = v;
}

// ---------------------------------------------------------------------------
// RoPE in-place. x: [B*T, H, 128]. cache: [T, 64, 2]. rnd -> tf32-round output.
// ---------------------------------------------------------------------------
__global__ void rope_kernel(float* __restrict__ x, const float* __restrict__ cache,
                            int H, int npairs, int rnd)
{
    int p = blockIdx.x * blockDim.x + threadIdx.x;
    if (p >= npairs) return;
    int i  = p & 63;
    int ph = p >> 6;
    int hh = ph % H;
    int bt = ph / H;
    int t  = bt & (T_ - 1);

    float* xp = x + ((size_t)bt * H + hh) * D_ + (i << 1);
    float2 xv = *(float2*)xp;
    float2 cs = *(const float2*)(cache + ((size_t)t * 64 + i) * 2);
    float2 o;
    o.x = xv.x * cs.x - xv.y * cs.y;
    o.y = xv.x * cs.y + xv.y * cs.x;
    if (rnd) {
        o.x = __uint_as_float(f2tf32(o.x));
        o.y = __uint_as_float(f2tf32(o.y));
    }
    *(float2*)xp = o;
}

// ---------------------------------------------------------------------------
// Tensor-core sliding-window attention (window 256, dilation 1), GQA 16:4.
// Block = (b, h, 128 queries). 8 warps; warp owns 16 query rows.
// Per 32-key tile: S[16x32] = Q@K^T via mma tf32 (Q frags in regs),
// in-register mask + exp (no-max softmax), P -> per-warp smem -> A-frags,
// O[16x128] += P@V via mma. cp.async double-buffered K/V tiles.
// K smem stride 132 / V 136 / P 36 -> all fragment LDS conflict-free.
// Expects K, V pre-rounded to tf32; Q rounded at frag build; Y tf32-rounded.
// ---------------------------------------------------------------------------
#define KST 132
#define VST 136
#define AT_KBYTES (32 * KST * 4)          // 16896
#define AT_VBYTES (32 * VST * 4)          // 17408
#define AT_STAGE  (AT_KBYTES + AT_VBYTES) // 34304
#define AT_PBYTES (16 * 36 * 4)           // 2304 per warp
#define AT_SMEM   (2 * AT_STAGE + 8 * AT_PBYTES)  // 87040

__global__ __launch_bounds__(256, 1) void attn_tc(
    const float* __restrict__ Q, const float* __restrict__ K,
    const float* __restrict__ V, float* __restrict__ Y)
{
    extern __shared__ __align__(128) char smem[];
    const uint32_t sb = smem_u32(smem);

    const int tid  = threadIdx.x;
    const int lane = tid & 31;
    const int w    = tid >> 5;
    const int g    = lane >> 2;
    const int tg   = lane & 3;
    const int b    = blockIdx.z;
    const int h    = blockIdx.y;
    const int c0   = blockIdx.x << 7;
    const int kvh  = h >> 2;
    const int tr   = c0 + (w << 4) + g;          // rows tr (c0/c1), tr+8 (c2/c3)

    float* Pbuf = (float*)(smem + 2 * AT_STAGE + w * AT_PBYTES);

    // Q fragments: qf[kc][4] covers rows (g, g+8) x d-cols (kc*8+tg, +4)
    uint32_t qf[16][4];
    {
        const float scale = 0.088388347648318447f;  // 1/sqrt(128)
        const float* q0 = Q + ((size_t)(b * T_ + tr) * NH + h) * D_;
        const float* q8 = q0 + (size_t)8 * NH * D_;
#pragma unroll
        for (int kc = 0; kc < 16; kc++) {
            qf[kc][0] = f2tf32(q0[kc * 8 + tg] * scale);
            qf[kc][1] = f2tf32(q8[kc * 8 + tg] * scale);
            qf[kc][2] = f2tf32(q0[kc * 8 + tg + 4] * scale);
            qf[kc][3] = f2tf32(q8[kc * 8 + tg + 4] * scale);
        }
    }

    float o[16][4];
#pragma unroll
    for (int i = 0; i < 16; i++)
#pragma unroll
        for (int e = 0; e < 4; e++) o[i][e] = 0.f;
    float l0 = 0.f, l1 = 0.f;

    auto load_tile = [&](int stage, int kbase) {
        const uint32_t kd = sb + stage * AT_STAGE;
        const uint32_t vd = kd + AT_KBYTES;
#pragma unroll
        for (int i = 0; i < 4; i++) {
            int idx = tid + (i << 8);     // 0..1023
            int row = idx >> 5;           // 0..31
            int seg = idx & 31;           // 16B segs across 512B row
            const size_t gofs =
                ((size_t)(b * T_ + kbase + row) * NKV + kvh) * D_ + ((size_t)seg << 2);
            cp16(kd + row * (KST * 4) + (seg << 4), K + gofs);
            cp16(vd + row * (VST * 4) + (seg << 4), V + gofs);
        }
    };

    const int tstart = (c0 >= 256) ? 0 : ((256 - c0) >> 5);
    load_tile(tstart & 1, c0 - 256 + (tstart << 5));
    CP_COMMIT();

    const int wq0 = c0 + (w << 4);

    for (int t = tstart; t < 12; t++) {
        const int kbase = c0 - 256 + (t << 5);
        const int s = t & 1;
        if (t + 1 < 12) {
            load_tile((t + 1) & 1, kbase + 32);
            CP_COMMIT();
            CP_WAIT1();
        } else {
            CP_WAIT0();
        }
        __syncthreads();

        const bool active = !(kbase > wq0 + 15 || kbase + 31 < wq0 - 255);
        if (active) {
            const float* Ksm = (const float*)(smem + s * AT_STAGE);
            const float* Vsm = (const float*)(smem + s * AT_STAGE + AT_KBYTES);

            // scores S[16 x 32]
            float sc[4][4];
#pragma unroll
            for (int nc = 0; nc < 4; nc++)
#pragma unroll
                for (int e = 0; e < 4; e++) sc[nc][e] = 0.f;

#pragma unroll
            for (int kc = 0; kc < 16; kc++) {
#pragma unroll
                for (int nc = 0; nc < 4; nc++) {
                    uint32_t bb[2];
                    bb[0] = __float_as_uint(Ksm[(nc * 8 + g) * KST + kc * 8 + tg]);
                    bb[1] = __float_as_uint(Ksm[(nc * 8 + g) * KST + kc * 8 + tg + 4]);
                    mma_tf32(sc[nc], qf[kc], bb);
                }
            }

            // mask + exp + P store (no-max softmax; scores O(1))
#pragma unroll
            for (int nc = 0; nc < 4; nc++) {
                const int col = kbase + nc * 8 + (tg << 1);
                float p0 = ((unsigned)(tr - col)       < 256u) ? __expf(sc[nc][0]) : 0.f;
                float p1 = ((unsigned)(tr - col - 1)   < 256u) ? __expf(sc[nc][1]) : 0.f;
                float p2 = ((unsigned)(tr + 8 - col)   < 256u) ? __expf(sc[nc][2]) : 0.f;
                float p3 = ((unsigned)(tr + 7 - col)   < 256u) ? __expf(sc[nc][3]) : 0.f;
                p0 = __uint_as_float(f2tf32(p0));
                p1 = __uint_as_float(f2tf32(p1));
                p2 = __uint_as_float(f2tf32(p2));
                p3 = __uint_as_float(f2tf32(p3));
                l0 += p0 + p1;
                l1 += p2 + p3;
                const int pc = nc * 8 + (tg << 1);
                Pbuf[g * 36 + pc]           = p0;
                Pbuf[g * 36 + pc + 1]       = p1;
                Pbuf[(g + 8) * 36 + pc]     = p2;
                Pbuf[(g + 8) * 36 + pc + 1] = p3;
            }
            __syncwarp();

            // O += P @ V
#pragma unroll
            for (int kc = 0; kc < 4; kc++) {
                uint32_t a[4];
                a[0] = __float_as_uint(Pbuf[g * 36 + kc * 8 + tg]);
                a[1] = __float_as_uint(Pbuf[(g + 8) * 36 + kc * 8 + tg]);
                a[2] = __float_as_uint(Pbuf[g * 36 + kc * 8 + tg + 4]);
                a[3] = __float_as_uint(Pbuf[(g + 8) * 36 + kc * 8 + tg + 4]);
#pragma unroll
                for (int nc = 0; nc < 16; nc++) {
                    uint32_t bb[2];
                    bb[0] = __float_as_uint(Vsm[(kc * 8 + tg) * VST + nc * 8 + g]);
                    bb[1] = __float_as_uint(Vsm[(kc * 8 + tg + 4) * VST + nc * 8 + g]);
                    mma_tf32(o[nc], a, bb);
                }
            }
            __syncwarp();
        }
        __syncthreads();
    }

    // row-sum reduction across tg lanes (lane bits 0-1)
    l0 += __shfl_xor_sync(0xffffffffu, l0, 1);
    l0 += __shfl_xor_sync(0xffffffffu, l0, 2);
    l1 += __shfl_xor_sync(0xffffffffu, l1, 1);
    l1 += __shfl_xor_sync(0xffffffffu, l1, 2);
    const float rl0 = 1.0f / l0;
    const float rl1 = 1.0f / l1;

    float* y0 = Y + ((size_t)(b * T_ + tr) * NH + h) * D_;
    float* y8 = y0 + (size_t)8 * NH * D_;
#pragma unroll
    for (int nc = 0; nc < 16; nc++) {
        const int d = nc * 8 + (tg << 1);
        *(float2*)(y0 + d) = make_float2(
            __uint_as_float(f2tf32(o[nc][0] * rl0)),
            __uint_as_float(f2tf32(o[nc][1] * rl0)));
        *(float2*)(y8 + d) = make_float2(
            __uint_as_float(f2tf32(o[nc][2] * rl1)),
            __uint_as_float(f2tf32(o[nc][3] * rl1)));
    }
}

// ---------------------------------------------------------------------------
// Launch. Inputs (metadata order): x, wq, wk, wv, wo, rope_cache. Out: fp32.
// ---------------------------------------------------------------------------
extern "C" void kernel_launch(void* const* d_in, const int* in_sizes, int n_in,
                              void* d_out, int out_size)
{
    const float* x    = (const float*)d_in[0];
    const float* wq   = (const float*)d_in[1];
    const float* wk   = (const float*)d_in[2];
    const float* wv   = (const float*)d_in[3];
    const float* wo   = (const float*)d_in[4];
    const float* rope = (const float*)d_in[5];
    float* out = (float*)d_out;

    float *pq, *pk, *pv, *py, *px, *pwq, *pwk, *pwv, *pwo;
    cudaGetSymbolAddress((void**)&pq,  g_q);
    cudaGetSymbolAddress((void**)&pk,  g_k);
    cudaGetSymbolAddress((void**)&pv,  g_v);
    cudaGetSymbolAddress((void**)&py,  g_y);
    cudaGetSymbolAddress((void**)&px,  g_x);
    cudaGetSymbolAddress((void**)&pwq, g_wq);
    cudaGetSymbolAddress((void**)&pwk, g_wk);
    cudaGetSymbolAddress((void**)&pwv, g_wv);
    cudaGetSymbolAddress((void**)&pwo, g_wo);

    cudaFuncSetAttribute(gemm_v2, cudaFuncAttributeMaxDynamicSharedMemorySize, GM_SMEM);
    cudaFuncSetAttribute(attn_tc, cudaFuncAttributeMaxDynamicSharedMemorySize, AT_SMEM);

    const int M = B_ * T_;  // 8192

    auto roundp = [&](float* dst, const float* src, int n) {
        int n4 = n / 4;
        round_tf32_kernel<<<(n4 + 255) / 256, 256>>>(dst, src, n4);
    };
    roundp(px,  x,  B_ * T_ * C_);
    roundp(pwq, wq, NH * D_ * C_);
    roundp(pwk, wk, NKV * D_ * C_);
    roundp(pwv, wv, NKV * D_ * C_);
    roundp(pwo, wo, C_ * C_);

    // QKV projections (v gets tf32-rounded output for the PV mma)
    gemm_v2<<<dim3((NH  * D_) / 256, M / 128), 256, GM_SMEM>>>(px, pwq, pq, M, NH  * D_, C_, 0);
    gemm_v2<<<dim3((NKV * D_) / 256, M / 128), 256, GM_SMEM>>>(px, pwk, pk, M, NKV * D_, C_, 0);
    gemm_v2<<<dim3((NKV * D_) / 256, M / 128), 256, GM_SMEM>>>(px, pwv, pv, M, NKV * D_, C_, 1);

    // RoPE: q plain fp32 (rounded at frag build), k rounded for QK^T mma
    const int nq = M * NH * 64;
    rope_kernel<<<(nq + 255) / 256, 256>>>(pq, rope, NH, nq, 0);
    const int nk = M * NKV * 64;
    rope_kernel<<<(nk + 255) / 256, 256>>>(pk, rope, NKV, nk, 1);

    // Tensor-core sliding-window attention -> y (tf32-rounded)
    attn_tc<<<dim3(T_ / 128, NH, B_), 256, AT_SMEM>>>(pq, pk, pv, py);

    // Output projection
    gemm_v2<<<dim3(C_ / 256, M / 128), 256, GM_SMEM>>>(py, pwo, out, M, C_, C_, 0);
}

// round 6
// speedup vs baseline: 2.7016x; 1.7602x over previous
#include <cuda_runtime.h>
#include <cuda_fp16.h>
#include <cstdint>
#include <cstddef>

#define B_  2
#define T_  4096
#define C_  2048
#define NH  16
#define NKV 4
#define D_  128

// Scratch (allocation-free rule: __device__ globals)
__device__ __align__(256) float  g_q [B_ * T_ * NH * D_];    // fp32 [B,T,H,D]
__device__ __align__(256) float  g_k [B_ * T_ * NKV * D_];   // fp32 (rope target)
__device__ __align__(256) float  g_v [B_ * T_ * NKV * D_];   // fp32 gemm out
__device__ __align__(256) __half g_kh[B_ * T_ * NKV * D_];   // fp16 [B,T,KV,D]
__device__ __align__(256) __half g_vt[B_ * NKV * D_ * T_];   // fp16 [B,KV,D,T]
__device__ __align__(256) __half g_yh[B_ * T_ * NH * D_];    // fp16 attention out
__device__ __align__(256) __half g_xh [B_ * T_ * C_];        // fp16 GEMM inputs
__device__ __align__(256) __half g_wqh[NH * D_ * C_];
__device__ __align__(256) __half g_wkh[NKV * D_ * C_];
__device__ __align__(256) __half g_wvh[NKV * D_ * C_];
__device__ __align__(256) __half g_woh[C_ * C_];

// ---------------------------------------------------------------------------
// Helpers (arch-agnostic PTX only — GPU-side build targets plain sm_103,
// which rejects all sm_103a-only features like tcgen05)
// ---------------------------------------------------------------------------
__device__ __forceinline__ uint32_t smem_u32(const void* p) {
    uint32_t a;
    asm("{ .reg .u64 t; cvta.to.shared.u64 t, %1; cvt.u32.u64 %0, t; }"
        : "=r"(a) : "l"(p));
    return a;
}

__device__ __forceinline__ void cp16(uint32_t dst, const void* src) {
    asm volatile("cp.async.cg.shared.global [%0], [%1], 16;\n"
                 :: "r"(dst), "l"(src));
}
#define CP_COMMIT() asm volatile("cp.async.commit_group;" ::: "memory")
#define CP_WAIT1()  asm volatile("cp.async.wait_group 1;" ::: "memory")
#define CP_WAIT0()  asm volatile("cp.async.wait_group 0;" ::: "memory")

// fp16 mma, fp32 accumulate: D[16x8] += A[16x16] * B[16x8]
__device__ __forceinline__ void mma_f16(float* c, const uint32_t* a, const uint32_t* b) {
    asm volatile(
        "mma.sync.aligned.m16n8k16.row.col.f32.f16.f16.f32 "
        "{%0,%1,%2,%3}, {%4,%5,%6,%7}, {%8,%9}, {%0,%1,%2,%3};\n"
        : "+f"(c[0]), "+f"(c[1]), "+f"(c[2]), "+f"(c[3])
        : "r"(a[0]), "r"(a[1]), "r"(a[2]), "r"(a[3]),
          "r"(b[0]), "r"(b[1]));
}

__device__ __forceinline__ uint32_t h2u(__half2 h) {
    return *reinterpret_cast<uint32_t*>(&h);
}

// ---------------------------------------------------------------------------
// fp16 GEMM: C[M,N] fp32 = Ah[M,K] * Bh[N,K]^T (fp16 in, fp32 accum).
// Block 128(M) x 256(N), k-tile 64 halves (128B rows), 8 warps (2Mx4N),
// warp tile 64x64. cp.async double-buffered. Smem row stride 72 halves ->
// all fragment LDS.32 bank-conflict-free.
// ---------------------------------------------------------------------------
#define HST 72
#define A_STAGE_B (128 * HST * 2)           // 18432
#define B_STAGE_B (256 * HST * 2)           // 36864
#define GM_SMEM   (2 * (A_STAGE_B + B_STAGE_B))  // 110592

__global__ __launch_bounds__(256, 1) void gemm_h(
    const __half* __restrict__ A, const __half* __restrict__ Bw,
    float* __restrict__ C, int M, int N, int K)
{
    extern __shared__ __align__(128) char smem[];
    const uint32_t sbase = smem_u32(smem);
    const uint32_t aoff[2] = { 0u, (uint32_t)A_STAGE_B };
    const uint32_t boff[2] = { 2u * A_STAGE_B, 2u * A_STAGE_B + B_STAGE_B };

    const int tid  = threadIdx.x;
    const int lane = tid & 31;
    const int warp = tid >> 5;
    const int g    = lane >> 2;
    const int tg   = lane & 3;
    const int wm   = warp & 1;
    const int wn   = warp >> 1;
    const int bm   = blockIdx.y << 7;
    const int bn   = blockIdx.x << 8;

    const int arow = tid >> 3;          // 0..31
    const int aseg = tid & 7;           // 16B segs (8 per 128B row)

    float acc[4][8][4];
#pragma unroll
    for (int i = 0; i < 4; i++)
#pragma unroll
        for (int j = 0; j < 8; j++)
#pragma unroll
            for (int e = 0; e < 4; e++) acc[i][j][e] = 0.f;

    const __half* Ag = A  + (size_t)bm * K;
    const __half* Bg = Bw + (size_t)bn * K;

    auto load_stage = [&](int sp, int kt) {
        const __half* As = Ag + (kt << 6);
        const __half* Bs = Bg + (kt << 6);
        const uint32_t ab = sbase + aoff[sp];
        const uint32_t bb = sbase + boff[sp];
#pragma unroll
        for (int i = 0; i < 4; i++) {
            int row = arow + (i << 5);
            cp16(ab + row * (HST * 2) + (aseg << 4), As + (size_t)row * K + (aseg << 3));
        }
#pragma unroll
        for (int i = 0; i < 8; i++) {
            int row = arow + (i << 5);
            cp16(bb + row * (HST * 2) + (aseg << 4), Bs + (size_t)row * K + (aseg << 3));
        }
    };

    const int nkt = K >> 6;   // 32 for K=2048
    load_stage(0, 0); CP_COMMIT();
    load_stage(1, 1); CP_COMMIT();

    for (int kt = 0; kt < nkt; kt++) {
        CP_WAIT1();
        __syncthreads();
        const int s = kt & 1;
        const uint32_t* Asm = (const uint32_t*)(smem + aoff[s]);
        const uint32_t* Bsm = (const uint32_t*)(smem + boff[s]);

#pragma unroll
        for (int ks = 0; ks < 4; ks++) {
            const int cw = ks * 8 + tg;   // half2 index within row
            uint32_t af[4][4];
            uint32_t bf[8][2];
#pragma unroll
            for (int mt = 0; mt < 4; mt++) {
                const int r0 = (wm << 6) + (mt << 4) + g;
                af[mt][0] = Asm[r0 * 36 + cw];
                af[mt][1] = Asm[(r0 + 8) * 36 + cw];
                af[mt][2] = Asm[r0 * 36 + cw + 4];
                af[mt][3] = Asm[(r0 + 8) * 36 + cw + 4];
            }
#pragma unroll
            for (int nt = 0; nt < 8; nt++) {
                const int r0 = (wn << 6) + (nt << 3) + g;
                bf[nt][0] = Bsm[r0 * 36 + cw];
                bf[nt][1] = Bsm[r0 * 36 + cw + 4];
            }
#pragma unroll
            for (int mt = 0; mt < 4; mt++)
#pragma unroll
                for (int nt = 0; nt < 8; nt++)
                    mma_f16(acc[mt][nt], af[mt], bf[nt]);
        }
        __syncthreads();
        if (kt + 2 < nkt) load_stage(s, kt + 2);
        CP_COMMIT();
    }

#pragma unroll
    for (int mt = 0; mt < 4; mt++) {
#pragma unroll
        for (int nt = 0; nt < 8; nt++) {
            const int row = bm + (wm << 6) + (mt << 4) + g;
            const int col = bn + (wn << 6) + (nt << 3) + (tg << 1);
            *(float2*)(C + (size_t)row * N + col) =
                make_float2(acc[mt][nt][0], acc[mt][nt][1]);
            *(float2*)(C + (size_t)(row + 8) * N + col) =
                make_float2(acc[mt][nt][2], acc[mt][nt][3]);
        }
    }
}

// ---------------------------------------------------------------------------
// fp32 -> fp16 conversion (RNE)
// ---------------------------------------------------------------------------
__global__ void cvt_f2h(__half* __restrict__ dst, const float* __restrict__ src, int n4)
{
    int i = blockIdx.x * blockDim.x + threadIdx.x;
    if (i >= n4) return;
    float4 v = ((const float4*)src)[i];
    __half2* d = (__half2*)dst + 2 * i;
    d[0] = __floats2half2_rn(v.x, v.y);
    d[1] = __floats2half2_rn(v.z, v.w);
}

// ---------------------------------------------------------------------------
// V transpose + convert: vt[b][kv][d][t] = (half) v[b][t][kv][d]
// ---------------------------------------------------------------------------
__global__ void transpose_v(__half* __restrict__ vt, const float* __restrict__ v)
{
    __shared__ float tile[32][33];
    const int t0 = blockIdx.x << 5;
    const int d0 = blockIdx.y << 5;
    const int bk = blockIdx.z;           // b*NKV + kv
    const int tx = threadIdx.x & 31;
    const int ty = threadIdx.x >> 5;

    const int b  = bk / NKV;
    const int kv = bk % NKV;

#pragma unroll
    for (int j = 0; j < 4; j++) {
        int tl = ty + (j << 3);
        tile[tl][tx] = v[((size_t)(b * T_ + t0 + tl) * NKV + kv) * D_ + d0 + tx];
    }
    __syncthreads();
#pragma unroll
    for (int j = 0; j < 4; j++) {
        int dl = ty + (j << 3);
        vt[((size_t)bk * D_ + d0 + dl) * T_ + t0 + tx] = __float2half_rn(tile[tx][dl]);
    }
}

// ---------------------------------------------------------------------------
// RoPE in-place (fp32). x: [B*T, H, 128]. cache: [T, 64, 2].
// ---------------------------------------------------------------------------
__global__ void rope_kernel(float* __restrict__ x, const float* __restrict__ cache,
                            int H, int npairs)
{
    int p = blockIdx.x * blockDim.x + threadIdx.x;
    if (p >= npairs) return;
    int i  = p & 63;
    int ph = p >> 6;
    int hh = ph % H;
    int bt = ph / H;
    int t  = bt & (T_ - 1);

    float* xp = x + ((size_t)bt * H + hh) * D_ + (i << 1);
    float2 xv = *(float2*)xp;
    float2 cs = *(const float2*)(cache + ((size_t)t * 64 + i) * 2);
    float2 o;
    o.x = xv.x * cs.x - xv.y * cs.y;
    o.y = xv.x * cs.y + xv.y * cs.x;
    *(float2*)xp = o;
}

// ---------------------------------------------------------------------------
// fp16 tensor-core sliding-window attention (window 256), GQA 16:4.
// QK: S[16x32] via m16n8k16 (Q frags in regs). P register-direct into PV
// A-fragments: a0=(row g, k-lo) a1=(row g+8, k-lo) a2=(row g, k-hi)
// a3=(row g+8, k-hi)  [the R5 bug was a1<->a2 swapped].
// PV: O[16x128] += P@V, V pre-transposed [d][t] in smem.
// ---------------------------------------------------------------------------
#define AKST 136
#define AVST 40
#define AT_KB (32 * AKST * 2)            // 8704
#define AT_VB (128 * AVST * 2)           // 10240
#define AT_STAGE (AT_KB + AT_VB)         // 18944
#define AT_SMEM  (2 * AT_STAGE)          // 37888

__global__ __launch_bounds__(256, 1) void attn_h(
    const float* __restrict__ Q, const __half* __restrict__ Kh,
    const __half* __restrict__ Vt, __half* __restrict__ Y)
{
    extern __shared__ __align__(128) char smem[];
    const uint32_t sb = smem_u32(smem);

    const int tid  = threadIdx.x;
    const int lane = tid & 31;
    const int w    = tid >> 5;
    const int g    = lane >> 2;
    const int tg   = lane & 3;
    const int b    = blockIdx.z;
    const int h    = blockIdx.y;
    const int c0   = blockIdx.x << 7;
    const int kvh  = h >> 2;
    const int tr   = c0 + (w << 4) + g;     // rows tr (c0/c1), tr+8 (c2/c3)

    // Q fragments: 8 k16 steps, 4 regs each
    uint32_t qf[8][4];
    {
        const float scale = 0.088388347648318447f;  // 1/sqrt(128)
        const float* q0 = Q + ((size_t)(b * T_ + tr) * NH + h) * D_;
        const float* q8 = q0 + (size_t)8 * NH * D_;
#pragma unroll
        for (int ks = 0; ks < 8; ks++) {
            const int c = ks * 16 + (tg << 1);
            qf[ks][0] = h2u(__floats2half2_rn(q0[c] * scale,     q0[c + 1] * scale));
            qf[ks][1] = h2u(__floats2half2_rn(q8[c] * scale,     q8[c + 1] * scale));
            qf[ks][2] = h2u(__floats2half2_rn(q0[c + 8] * scale, q0[c + 9] * scale));
            qf[ks][3] = h2u(__floats2half2_rn(q8[c + 8] * scale, q8[c + 9] * scale));
        }
    }

    float o[16][4];
#pragma unroll
    for (int i = 0; i < 16; i++)
#pragma unroll
        for (int e = 0; e < 4; e++) o[i][e] = 0.f;
    float l0 = 0.f, l1 = 0.f;

    auto load_tile = [&](int stage, int kbase) {
        const uint32_t kd = sb + stage * AT_STAGE;
        const uint32_t vd = kd + AT_KB;
#pragma unroll
        for (int i = 0; i < 2; i++) {
            int idx = tid + (i << 8);           // 0..511
            int row = idx >> 4, seg = idx & 15;
            cp16(kd + row * (AKST * 2) + (seg << 4),
                 Kh + ((size_t)(b * T_ + kbase + row) * NKV + kvh) * D_ + (seg << 3));
        }
#pragma unroll
        for (int i = 0; i < 2; i++) {
            int idx = tid + (i << 8);
            int row = idx >> 2, seg = idx & 3;
            cp16(vd + row * (AVST * 2) + (seg << 4),
                 Vt + ((size_t)(b * NKV + kvh) * D_ + row) * T_ + kbase + (seg << 3));
        }
    };

    const int tstart = (c0 >= 256) ? 0 : ((256 - c0) >> 5);
    load_tile(tstart & 1, c0 - 256 + (tstart << 5));
    CP_COMMIT();

    const int wq0 = c0 + (w << 4);

    for (int t = tstart; t < 12; t++) {
        const int kbase = c0 - 256 + (t << 5);
        const int s = t & 1;
        if (t + 1 < 12) {
            load_tile((t + 1) & 1, kbase + 32);
            CP_COMMIT();
            CP_WAIT1();
        } else {
            CP_WAIT0();
        }
        __syncthreads();

        const bool active = !(kbase > wq0 + 15 || kbase + 31 < wq0 - 255);
        if (active) {
            const uint32_t* Ksm = (const uint32_t*)(smem + s * AT_STAGE);
            const uint32_t* Vsm = (const uint32_t*)(smem + s * AT_STAGE + AT_KB);

            // S[16 x 32]
            float sc[4][4];
#pragma unroll
            for (int nc = 0; nc < 4; nc++)
#pragma unroll
                for (int e = 0; e < 4; e++) sc[nc][e] = 0.f;

#pragma unroll
            for (int ks = 0; ks < 8; ks++) {
                const int cw = ks * 8 + tg;    // half2 index within K row
#pragma unroll
                for (int nc = 0; nc < 4; nc++) {
                    const int kr = (nc * 8 + g) * 68;   // AKST/2
                    uint32_t bb[2];
                    bb[0] = Ksm[kr + cw];
                    bb[1] = Ksm[kr + cw + 4];
                    mma_f16(sc[nc], qf[ks], bb);
                }
            }

            // mask + exp; P -> PV A-fragments (registers only)
            uint32_t pa[2][4];
#pragma unroll
            for (int nc = 0; nc < 4; nc++) {
                const int col = kbase + nc * 8 + (tg << 1);
                float p0 = ((unsigned)(tr - col)     < 256u) ? __expf(sc[nc][0]) : 0.f;
                float p1 = ((unsigned)(tr - col - 1) < 256u) ? __expf(sc[nc][1]) : 0.f;
                float p2 = ((unsigned)(tr + 8 - col) < 256u) ? __expf(sc[nc][2]) : 0.f;
                float p3 = ((unsigned)(tr + 7 - col) < 256u) ? __expf(sc[nc][3]) : 0.f;
                l0 += p0 + p1;
                l1 += p2 + p3;
                const int kc = nc >> 1;       // PV k-step (16 keys each)
                const int hi = nc & 1;        // low/high key octet within k16
                pa[kc][2 * hi]     = h2u(__floats2half2_rn(p0, p1));  // row g
                pa[kc][2 * hi + 1] = h2u(__floats2half2_rn(p2, p3));  // row g+8
            }

            // O += P @ V  (Vt smem: row = d, 32 keys per row)
#pragma unroll
            for (int kc = 0; kc < 2; kc++) {
                const int cw = kc * 8 + tg;   // half2 key index within Vt row
#pragma unroll
                for (int nc = 0; nc < 16; nc++) {
                    const int vr = (nc * 8 + g) * 20;   // AVST/2
                    uint32_t bb[2];
                    bb[0] = Vsm[vr + cw];
                    bb[1] = Vsm[vr + cw + 4];
                    mma_f16(o[nc], pa[kc], bb);
                }
            }
        }
        __syncthreads();
    }

    // row-sum across tg lanes
    l0 += __shfl_xor_sync(0xffffffffu, l0, 1);
    l0 += __shfl_xor_sync(0xffffffffu, l0, 2);
    l1 += __shfl_xor_sync(0xffffffffu, l1, 1);
    l1 += __shfl_xor_sync(0xffffffffu, l1, 2);
    const float rl0 = 1.0f / l0;
    const float rl1 = 1.0f / l1;

    __half2* y0 = (__half2*)(Y + ((size_t)(b * T_ + tr) * NH + h) * D_);
    __half2* y8 = (__half2*)(Y + ((size_t)(b * T_ + tr + 8) * NH + h) * D_);
#pragma unroll
    for (int nc = 0; nc < 16; nc++) {
        const int dw = nc * 4 + tg;   // half2 index within 128-d row
        y0[dw] = __floats2half2_rn(o[nc][0] * rl0, o[nc][1] * rl0);
        y8[dw] = __floats2half2_rn(o[nc][2] * rl1, o[nc][3] * rl1);
    }
}

// ---------------------------------------------------------------------------
// k fp32 -> fp16 (post-rope)
// ---------------------------------------------------------------------------
__global__ void cvt_k(__half* __restrict__ dst, const float* __restrict__ src, int n4)
{
    int i = blockIdx.x * blockDim.x + threadIdx.x;
    if (i >= n4) return;
    float4 v = ((const float4*)src)[i];
    __half2* d = (__half2*)dst + 2 * i;
    d[0] = __floats2half2_rn(v.x, v.y);
    d[1] = __floats2half2_rn(v.z, v.w);
}

// ---------------------------------------------------------------------------
// Launch. Inputs (metadata order): x, wq, wk, wv, wo, rope_cache. Out: fp32.
// ---------------------------------------------------------------------------
extern "C" void kernel_launch(void* const* d_in, const int* in_sizes, int n_in,
                              void* d_out, int out_size)
{
    const float* x    = (const float*)d_in[0];
    const float* wq   = (const float*)d_in[1];
    const float* wk   = (const float*)d_in[2];
    const float* wv   = (const float*)d_in[3];
    const float* wo   = (const float*)d_in[4];
    const float* rope = (const float*)d_in[5];
    float* out = (float*)d_out;

    float *pq, *pk, *pv;
    __half *pkh, *pvt, *pyh, *pxh, *pwqh, *pwkh, *pwvh, *pwoh;
    cudaGetSymbolAddress((void**)&pq,   g_q);
    cudaGetSymbolAddress((void**)&pk,   g_k);
    cudaGetSymbolAddress((void**)&pv,   g_v);
    cudaGetSymbolAddress((void**)&pkh,  g_kh);
    cudaGetSymbolAddress((void**)&pvt,  g_vt);
    cudaGetSymbolAddress((void**)&pyh,  g_yh);
    cudaGetSymbolAddress((void**)&pxh,  g_xh);
    cudaGetSymbolAddress((void**)&pwqh, g_wqh);
    cudaGetSymbolAddress((void**)&pwkh, g_wkh);
    cudaGetSymbolAddress((void**)&pwvh, g_wvh);
    cudaGetSymbolAddress((void**)&pwoh, g_woh);

    cudaFuncSetAttribute(gemm_h, cudaFuncAttributeMaxDynamicSharedMemorySize, GM_SMEM);
    cudaFuncSetAttribute(attn_h, cudaFuncAttributeMaxDynamicSharedMemorySize, AT_SMEM);

    const int M = B_ * T_;  // 8192

    auto cvt = [&](__half* dst, const float* src, int n) {
        int n4 = n / 4;
        cvt_f2h<<<(n4 + 255) / 256, 256>>>(dst, src, n4);
    };
    cvt(pxh,  x,  B_ * T_ * C_);
    cvt(pwqh, wq, NH * D_ * C_);
    cvt(pwkh, wk, NKV * D_ * C_);
    cvt(pwvh, wv, NKV * D_ * C_);
    cvt(pwoh, wo, C_ * C_);

    // QKV projections (fp16 in, fp32 out)
    gemm_h<<<dim3((NH  * D_) / 256, M / 128), 256, GM_SMEM>>>(pxh, pwqh, pq, M, NH  * D_, C_);
    gemm_h<<<dim3((NKV * D_) / 256, M / 128), 256, GM_SMEM>>>(pxh, pwkh, pk, M, NKV * D_, C_);
    gemm_h<<<dim3((NKV * D_) / 256, M / 128), 256, GM_SMEM>>>(pxh, pwvh, pv, M, NKV * D_, C_);

    // RoPE (fp32 in-place)
    const int nq = M * NH * 64;
    rope_kernel<<<(nq + 255) / 256, 256>>>(pq, rope, NH, nq);
    const int nk = M * NKV * 64;
    rope_kernel<<<(nk + 255) / 256, 256>>>(pk, rope, NKV, nk);

    // k -> fp16 ; v -> fp16 transposed [b][kv][d][t]
    const int nkel = M * NKV * D_;
    cvt_k<<<(nkel / 4 + 255) / 256, 256>>>(pkh, pk, nkel / 4);
    transpose_v<<<dim3(T_ / 32, D_ / 32, B_ * NKV), 256>>>(pvt, pv);

    // fp16 tensor-core sliding-window attention -> yh (fp16)
    attn_h<<<dim3(T_ / 128, NH, B_), 256, AT_SMEM>>>(pq, pkh, pvt, pyh);

    // Output projection (fp16 in, fp32 out)
    gemm_h<<<dim3(C_ / 256, M / 128), 256, GM_SMEM>>>(pyh, pwoh, out, M, C_, C_);
}

// round 7
// speedup vs baseline: 2.9133x; 1.0784x over previous
#include <cuda_runtime.h>
#include <cuda_fp16.h>
#include <cstdint>
#include <cstddef>

#define B_  2
#define T_  4096
#define C_  2048
#define NH  16
#define NKV 4
#define D_  128

// Scratch (allocation-free rule: __device__ globals)
__device__ __align__(256) __half g_qh[B_ * T_ * NH * D_];    // rope'd fp16 Q
__device__ __align__(256) __half g_kh[B_ * T_ * NKV * D_];   // rope'd fp16 K
__device__ __align__(256) __half g_vh[B_ * T_ * NKV * D_];   // fp16 V [B,T,KV,D]
__device__ __align__(256) __half g_yh[B_ * T_ * NH * D_];    // fp16 attention out
__device__ __align__(256) __half g_xh [B_ * T_ * C_];        // fp16 GEMM inputs
__device__ __align__(256) __half g_wqh[NH * D_ * C_];
__device__ __align__(256) __half g_wkh[NKV * D_ * C_];
__device__ __align__(256) __half g_wvh[NKV * D_ * C_];
__device__ __align__(256) __half g_woh[C_ * C_];

// ---------------------------------------------------------------------------
// Helpers (arch-agnostic PTX only — GPU-side build targets plain sm_103,
// which rejects all sm_103a-only features like tcgen05)
// ---------------------------------------------------------------------------
__device__ __forceinline__ uint32_t smem_u32(const void* p) {
    uint32_t a;
    asm("{ .reg .u64 t; cvta.to.shared.u64 t, %1; cvt.u32.u64 %0, t; }"
        : "=r"(a) : "l"(p));
    return a;
}

__device__ __forceinline__ void cp16(uint32_t dst, const void* src) {
    asm volatile("cp.async.cg.shared.global [%0], [%1], 16;\n"
                 :: "r"(dst), "l"(src));
}
#define CP_COMMIT() asm volatile("cp.async.commit_group;" ::: "memory")
#define CP_WAIT1()  asm volatile("cp.async.wait_group 1;" ::: "memory")
#define CP_WAIT0()  asm volatile("cp.async.wait_group 0;" ::: "memory")

// fp16 mma, fp32 accumulate: D[16x8] += A[16x16] * B[16x8]
__device__ __forceinline__ void mma_f16(float* c, const uint32_t* a, const uint32_t* b) {
    asm volatile(
        "mma.sync.aligned.m16n8k16.row.col.f32.f16.f16.f32 "
        "{%0,%1,%2,%3}, {%4,%5,%6,%7}, {%8,%9}, {%0,%1,%2,%3};\n"
        : "+f"(c[0]), "+f"(c[1]), "+f"(c[2]), "+f"(c[3])
        : "r"(a[0]), "r"(a[1]), "r"(a[2]), "r"(a[3]),
          "r"(b[0]), "r"(b[1]));
}

__device__ __forceinline__ void ldsm_x4(uint32_t& r0, uint32_t& r1,
                                        uint32_t& r2, uint32_t& r3, uint32_t addr) {
    asm volatile("ldmatrix.sync.aligned.m8n8.x4.shared.b16 {%0,%1,%2,%3}, [%4];"
                 : "=r"(r0), "=r"(r1), "=r"(r2), "=r"(r3) : "r"(addr));
}

__device__ __forceinline__ void ldsm_x4_t(uint32_t& r0, uint32_t& r1,
                                          uint32_t& r2, uint32_t& r3, uint32_t addr) {
    asm volatile("ldmatrix.sync.aligned.m8n8.x4.trans.shared.b16 {%0,%1,%2,%3}, [%4];"
                 : "=r"(r0), "=r"(r1), "=r"(r2), "=r"(r3) : "r"(addr));
}

__device__ __forceinline__ uint32_t h2u(__half2 h) {
    return *reinterpret_cast<uint32_t*>(&h);
}

__device__ __forceinline__ float ex2(float x) {
    float r;
    asm("ex2.approx.f32 %0, %1;" : "=f"(r) : "f"(x));
    return r;
}

// ---------------------------------------------------------------------------
// fp16 GEMM with fused epilogue.
// C[M,N] = Ah[M,K] * Bh[N,K]^T (fp16 in, fp32 accum).
// MODE 0: fp32 out. MODE 1: RoPE + fp16 out (Q,K). MODE 2: fp16 out (V).
// Block 128x256, k-tile 64 halves, 8 warps (2Mx4N), warp 64x64,
// fragment loads via ldmatrix.x4, cp.async double-buffered.
// ---------------------------------------------------------------------------
#define HST 72
#define A_STAGE_B (128 * HST * 2)           // 18432
#define B_STAGE_B (256 * HST * 2)           // 36864
#define GM_SMEM   (2 * (A_STAGE_B + B_STAGE_B))  // 110592

template <int MODE>
__global__ __launch_bounds__(256, 1) void gemm_h(
    const __half* __restrict__ A, const __half* __restrict__ Bw,
    void* __restrict__ Cv, const float* __restrict__ rope, int M, int N, int K)
{
    extern __shared__ __align__(128) char smem[];
    const uint32_t sbase = smem_u32(smem);
    const uint32_t aoff[2] = { 0u, (uint32_t)A_STAGE_B };
    const uint32_t boff[2] = { 2u * A_STAGE_B, 2u * A_STAGE_B + B_STAGE_B };

    const int tid  = threadIdx.x;
    const int lane = tid & 31;
    const int warp = tid >> 5;
    const int g    = lane >> 2;
    const int tg   = lane & 3;
    const int wm   = warp & 1;
    const int wn   = warp >> 1;
    const int bm   = blockIdx.y << 7;
    const int bn   = blockIdx.x << 8;

    const int arow = tid >> 3;          // 0..31
    const int aseg = tid & 7;           // 16B segs (8 per 128B row)

    // ldmatrix lane offsets (byte units)
    const uint32_t a_lrow = (lane & 7) + (((lane >> 3) & 1) << 3);
    const uint32_t a_kofb = (lane >> 4) << 4;
    const uint32_t b_lrow = (lane & 7) + ((lane >> 4) << 3);
    const uint32_t b_kofb = ((lane >> 3) & 1) << 4;

    float acc[4][8][4];
#pragma unroll
    for (int i = 0; i < 4; i++)
#pragma unroll
        for (int j = 0; j < 8; j++)
#pragma unroll
            for (int e = 0; e < 4; e++) acc[i][j][e] = 0.f;

    const __half* Ag = A  + (size_t)bm * K;
    const __half* Bg = Bw + (size_t)bn * K;

    auto load_stage = [&](int sp, int kt) {
        const __half* As = Ag + (kt << 6);
        const __half* Bs = Bg + (kt << 6);
        const uint32_t ab = sbase + aoff[sp];
        const uint32_t bb = sbase + boff[sp];
#pragma unroll
        for (int i = 0; i < 4; i++) {
            int row = arow + (i << 5);
            cp16(ab + row * (HST * 2) + (aseg << 4), As + (size_t)row * K + (aseg << 3));
        }
#pragma unroll
        for (int i = 0; i < 8; i++) {
            int row = arow + (i << 5);
            cp16(bb + row * (HST * 2) + (aseg << 4), Bs + (size_t)row * K + (aseg << 3));
        }
    };

    const int nkt = K >> 6;   // 32 for K=2048
    load_stage(0, 0); CP_COMMIT();
    load_stage(1, 1); CP_COMMIT();

    for (int kt = 0; kt < nkt; kt++) {
        CP_WAIT1();
        __syncthreads();
        const int s = kt & 1;
        const uint32_t Asm = sbase + aoff[s];
        const uint32_t Bsm = sbase + boff[s];

#pragma unroll
        for (int ks = 0; ks < 4; ks++) {
            uint32_t af[4][4];
            uint32_t bf[8][2];
#pragma unroll
            for (int mt = 0; mt < 4; mt++) {
                const uint32_t addr = Asm +
                    ((wm << 6) + (mt << 4) + a_lrow) * (HST * 2) + (ks << 5) + a_kofb;
                ldsm_x4(af[mt][0], af[mt][1], af[mt][2], af[mt][3], addr);
            }
#pragma unroll
            for (int ntp = 0; ntp < 4; ntp++) {
                const uint32_t addr = Bsm +
                    ((wn << 6) + (ntp << 4) + b_lrow) * (HST * 2) + (ks << 5) + b_kofb;
                ldsm_x4(bf[2 * ntp][0], bf[2 * ntp][1],
                        bf[2 * ntp + 1][0], bf[2 * ntp + 1][1], addr);
            }
#pragma unroll
            for (int mt = 0; mt < 4; mt++)
#pragma unroll
                for (int nt = 0; nt < 8; nt++)
                    mma_f16(acc[mt][nt], af[mt], bf[nt]);
        }
        __syncthreads();
        if (kt + 2 < nkt) load_stage(s, kt + 2);
        CP_COMMIT();
    }

#pragma unroll
    for (int mt = 0; mt < 4; mt++) {
#pragma unroll
        for (int nt = 0; nt < 8; nt++) {
            float v0 = acc[mt][nt][0], v1 = acc[mt][nt][1];
            float v2 = acc[mt][nt][2], v3 = acc[mt][nt][3];
            const int row = bm + (wm << 6) + (mt << 4) + g;
            const int col = bn + (wn << 6) + (nt << 3) + (tg << 1);
            if (MODE == 1) {
                const int t = row & (T_ - 1);
                const int d = col & 127;
                float2 cs0 = *(const float2*)(rope + (size_t)t * 128 + d);
                float2 cs8 = *(const float2*)(rope + (size_t)(t + 8) * 128 + d);
                float o0 = v0 * cs0.x - v1 * cs0.y;
                float o1 = v0 * cs0.y + v1 * cs0.x;
                float o2 = v2 * cs8.x - v3 * cs8.y;
                float o3 = v2 * cs8.y + v3 * cs8.x;
                v0 = o0; v1 = o1; v2 = o2; v3 = o3;
            }
            if (MODE == 0) {
                float* C = (float*)Cv;
                *(float2*)(C + (size_t)row * N + col) = make_float2(v0, v1);
                *(float2*)(C + (size_t)(row + 8) * N + col) = make_float2(v2, v3);
            } else {
                __half* C = (__half*)Cv;
                *(__half2*)(C + (size_t)row * N + col) = __floats2half2_rn(v0, v1);
                *(__half2*)(C + (size_t)(row + 8) * N + col) = __floats2half2_rn(v2, v3);
            }
        }
    }
}

// ---------------------------------------------------------------------------
// fp32 -> fp16 conversion (RNE)
// ---------------------------------------------------------------------------
__global__ void cvt_f2h(__half* __restrict__ dst, const float* __restrict__ src, int n4)
{
    int i = blockIdx.x * blockDim.x + threadIdx.x;
    if (i >= n4) return;
    float4 v = ((const float4*)src)[i];
    __half2* d = (__half2*)dst + 2 * i;
    d[0] = __floats2half2_rn(v.x, v.y);
    d[1] = __floats2half2_rn(v.z, v.w);
}

// ---------------------------------------------------------------------------
// fp16 tensor-core sliding-window attention (window 256), GQA 16:4.
// QK: S[16x32] via m16n8k16, K B-frags via ldmatrix.x4, Q frags register-
// resident (raw fp16; 1/sqrt(d) folded into exp2 scale). P register-direct
// into PV A-fragments. PV B-frags via ldmatrix.x4.trans on un-transposed V.
// K/V smem rows 272B (stride 136 halves) -> conflict-free ldmatrix.
// ---------------------------------------------------------------------------
#define AKST 136
#define AT_KB (32 * AKST * 2)            // 8704
#define AT_STAGE (2 * AT_KB)             // 17408
#define AT_SMEM  (2 * AT_STAGE)          // 34816

__global__ __launch_bounds__(256, 1) void attn_h(
    const __half* __restrict__ Qh, const __half* __restrict__ Kh,
    const __half* __restrict__ Vh, __half* __restrict__ Y)
{
    extern __shared__ __align__(128) char smem[];
    const uint32_t sb = smem_u32(smem);

    const int tid  = threadIdx.x;
    const int lane = tid & 31;
    const int w    = tid >> 5;
    const int g    = lane >> 2;
    const int tg   = lane & 3;
    const int b    = blockIdx.z;
    const int h    = blockIdx.y;
    const int c0   = blockIdx.x << 7;
    const int kvh  = h >> 2;
    const int tr   = c0 + (w << 4) + g;     // rows tr (c0/c1), tr+8 (c2/c3)

    // exp2 scale: log2(e)/sqrt(128)
    const float EXPSCALE = 0.1275174325f;

    // ldmatrix lane offsets (bytes)
    const uint32_t qk_lbase = (lane & 7) * (AKST * 2) + ((lane >> 3) << 4);
    const uint32_t pv_lbase = ((((lane >> 3) & 1) << 3) + (lane & 7)) * (AKST * 2)
                              + ((lane >> 4) << 4);

    // Q fragments: 8 k16 steps, 4 regs each — raw fp16 loads
    uint32_t qf[8][4];
    {
        const __half* q0 = Qh + ((size_t)(b * T_ + tr) * NH + h) * D_;
        const __half* q8 = q0 + (size_t)8 * NH * D_;
#pragma unroll
        for (int ks = 0; ks < 8; ks++) {
            const int c = ks * 16 + (tg << 1);
            qf[ks][0] = *(const uint32_t*)(q0 + c);
            qf[ks][1] = *(const uint32_t*)(q8 + c);
            qf[ks][2] = *(const uint32_t*)(q0 + c + 8);
            qf[ks][3] = *(const uint32_t*)(q8 + c + 8);
        }
    }

    float o[16][4];
#pragma unroll
    for (int i = 0; i < 16; i++)
#pragma unroll
        for (int e = 0; e < 4; e++) o[i][e] = 0.f;
    float l0 = 0.f, l1 = 0.f;

    auto load_tile = [&](int stage, int kbase) {
        const uint32_t kd = sb + stage * AT_STAGE;
        const uint32_t vd = kd + AT_KB;
#pragma unroll
        for (int i = 0; i < 2; i++) {
            int idx = tid + (i << 8);           // 0..511
            int row = idx >> 4, seg = idx & 15;
            const size_t gofs =
                ((size_t)(b * T_ + kbase + row) * NKV + kvh) * D_ + (seg << 3);
            cp16(kd + row * (AKST * 2) + (seg << 4), Kh + gofs);
            cp16(vd + row * (AKST * 2) + (seg << 4), Vh + gofs);
        }
    };

    const int tstart = (c0 >= 256) ? 0 : ((256 - c0) >> 5);
    load_tile(tstart & 1, c0 - 256 + (tstart << 5));
    CP_COMMIT();

    const int wq0 = c0 + (w << 4);

    for (int t = tstart; t < 12; t++) {
        const int kbase = c0 - 256 + (t << 5);
        const int s = t & 1;
        if (t + 1 < 12) {
            load_tile((t + 1) & 1, kbase + 32);
            CP_COMMIT();
            CP_WAIT1();
        } else {
            CP_WAIT0();
        }
        __syncthreads();

        const bool active = !(kbase > wq0 + 15 || kbase + 31 < wq0 - 255);
        if (active) {
            const uint32_t Ksm = sb + s * AT_STAGE;
            const uint32_t Vsm = Ksm + AT_KB;

            // S[16 x 32]
            float sc[4][4];
#pragma unroll
            for (int nc = 0; nc < 4; nc++)
#pragma unroll
                for (int e = 0; e < 4; e++) sc[nc][e] = 0.f;

#pragma unroll
            for (int ksp = 0; ksp < 4; ksp++) {
#pragma unroll
                for (int nc = 0; nc < 4; nc++) {
                    uint32_t r0, r1, r2, r3;
                    const uint32_t addr = Ksm + nc * (8 * AKST * 2) + (ksp << 6) + qk_lbase;
                    ldsm_x4(r0, r1, r2, r3, addr);
                    uint32_t blo[2] = { r0, r1 };
                    uint32_t bhi[2] = { r2, r3 };
                    mma_f16(sc[nc], qf[2 * ksp],     blo);
                    mma_f16(sc[nc], qf[2 * ksp + 1], bhi);
                }
            }

            // mask + exp; P -> PV A-fragments (registers only)
            uint32_t pa[2][4];
#pragma unroll
            for (int nc = 0; nc < 4; nc++) {
                const int col = kbase + nc * 8 + (tg << 1);
                float p0 = ((unsigned)(tr - col)     < 256u) ? ex2(sc[nc][0] * EXPSCALE) : 0.f;
                float p1 = ((unsigned)(tr - col - 1) < 256u) ? ex2(sc[nc][1] * EXPSCALE) : 0.f;
                float p2 = ((unsigned)(tr + 8 - col) < 256u) ? ex2(sc[nc][2] * EXPSCALE) : 0.f;
                float p3 = ((unsigned)(tr + 7 - col) < 256u) ? ex2(sc[nc][3] * EXPSCALE) : 0.f;
                l0 += p0 + p1;
                l1 += p2 + p3;
                const int kc = nc >> 1;       // PV k-step (16 keys each)
                const int hi = nc & 1;        // low/high key octet within k16
                pa[kc][2 * hi]     = h2u(__floats2half2_rn(p0, p1));  // row g
                pa[kc][2 * hi + 1] = h2u(__floats2half2_rn(p2, p3));  // row g+8
            }

            // O += P @ V  (V smem [key][d], trans-ldmatrix -> B frags)
#pragma unroll
            for (int kc = 0; kc < 2; kc++) {
#pragma unroll
                for (int ncp = 0; ncp < 8; ncp++) {
                    uint32_t r0, r1, r2, r3;
                    const uint32_t addr = Vsm + kc * (16 * AKST * 2) + (ncp << 5) + pv_lbase;
                    ldsm_x4_t(r0, r1, r2, r3, addr);
                    uint32_t blo[2] = { r0, r1 };
                    uint32_t bhi[2] = { r2, r3 };
                    mma_f16(o[2 * ncp],     pa[kc], blo);
                    mma_f16(o[2 * ncp + 1], pa[kc], bhi);
                }
            }
        }
        __syncthreads();
    }

    // row-sum across tg lanes
    l0 += __shfl_xor_sync(0xffffffffu, l0, 1);
    l0 += __shfl_xor_sync(0xffffffffu, l0, 2);
    l1 += __shfl_xor_sync(0xffffffffu, l1, 1);
    l1 += __shfl_xor_sync(0xffffffffu, l1, 2);
    const float rl0 = 1.0f / l0;
    const float rl1 = 1.0f / l1;

    __half2* y0 = (__half2*)(Y + ((size_t)(b * T_ + tr) * NH + h) * D_);
    __half2* y8 = (__half2*)(Y + ((size_t)(b * T_ + tr + 8) * NH + h) * D_);
#pragma unroll
    for (int nc = 0; nc < 16; nc++) {
        const int dw = nc * 4 + tg;   // half2 index within 128-d row
        y0[dw] = __floats2half2_rn(o[nc][0] * rl0, o[nc][1] * rl0);
        y8[dw] = __floats2half2_rn(o[nc][2] * rl1, o[nc][3] * rl1);
    }
}

// ---------------------------------------------------------------------------
// Launch. Inputs (metadata order): x, wq, wk, wv, wo, rope_cache. Out: fp32.
// ---------------------------------------------------------------------------
extern "C" void kernel_launch(void* const* d_in, const int* in_sizes, int n_in,
                              void* d_out, int out_size)
{
    const float* x    = (const float*)d_in[0];
    const float* wq   = (const float*)d_in[1];
    const float* wk   = (const float*)d_in[2];
    const float* wv   = (const float*)d_in[3];
    const float* wo   = (const float*)d_in[4];
    const float* rope = (const float*)d_in[5];
    float* out = (float*)d_out;

    __half *pqh, *pkh, *pvh, *pyh, *pxh, *pwqh, *pwkh, *pwvh, *pwoh;
    cudaGetSymbolAddress((void**)&pqh,  g_qh);
    cudaGetSymbolAddress((void**)&pkh,  g_kh);
    cudaGetSymbolAddress((void**)&pvh,  g_vh);
    cudaGetSymbolAddress((void**)&pyh,  g_yh);
    cudaGetSymbolAddress((void**)&pxh,  g_xh);
    cudaGetSymbolAddress((void**)&pwqh, g_wqh);
    cudaGetSymbolAddress((void**)&pwkh, g_wkh);
    cudaGetSymbolAddress((void**)&pwvh, g_wvh);
    cudaGetSymbolAddress((void**)&pwoh, g_woh);

    cudaFuncSetAttribute(gemm_h<0>, cudaFuncAttributeMaxDynamicSharedMemorySize, GM_SMEM);
    cudaFuncSetAttribute(gemm_h<1>, cudaFuncAttributeMaxDynamicSharedMemorySize, GM_SMEM);
    cudaFuncSetAttribute(gemm_h<2>, cudaFuncAttributeMaxDynamicSharedMemorySize, GM_SMEM);
    cudaFuncSetAttribute(attn_h,    cudaFuncAttributeMaxDynamicSharedMemorySize, AT_SMEM);

    const int M = B_ * T_;  // 8192

    auto cvt = [&](__half* dst, const float* src, int n) {
        int n4 = n / 4;
        cvt_f2h<<<(n4 + 255) / 256, 256>>>(dst, src, n4);
    };
    cvt(pxh,  x,  B_ * T_ * C_);
    cvt(pwqh, wq, NH * D_ * C_);
    cvt(pwkh, wk, NKV * D_ * C_);
    cvt(pwvh, wv, NKV * D_ * C_);
    cvt(pwoh, wo, C_ * C_);

    // QKV projections with fused epilogues (rope+fp16 for Q/K, fp16 for V)
    gemm_h<1><<<dim3((NH  * D_) / 256, M / 128), 256, GM_SMEM>>>(
        pxh, pwqh, pqh, rope, M, NH * D_, C_);
    gemm_h<1><<<dim3((NKV * D_) / 256, M / 128), 256, GM_SMEM>>>(
        pxh, pwkh, pkh, rope, M, NKV * D_, C_);
    gemm_h<2><<<dim3((NKV * D_) / 256, M / 128), 256, GM_SMEM>>>(
        pxh, pwvh, pvh, nullptr, M, NKV * D_, C_);

    // fp16 tensor-core sliding-window attention -> yh (fp16)
    attn_h<<<dim3(T_ / 128, NH, B_), 256, AT_SMEM>>>(pqh, pkh, pvh, pyh);

    // Output projection (fp16 in, fp32 out)
    gemm_h<0><<<dim3(C_ / 256, M / 128), 256, GM_SMEM>>>(
        pyh, pwoh, out, nullptr, M, C_, C_);
}

// round 8
// speedup vs baseline: 3.0300x; 1.0400x over previous
#include <cuda_runtime.h>
#include <cuda_fp16.h>
#include <cstdint>
#include <cstddef>

#define B_  2
#define T_  4096
#define C_  2048
#define NH  16
#define NKV 4
#define D_  128

// Scratch (allocation-free rule: __device__ globals)
__device__ __align__(256) __half g_qh[B_ * T_ * NH * D_];    // rope'd fp16 Q
__device__ __align__(256) __half g_kh[B_ * T_ * NKV * D_];   // rope'd fp16 K
__device__ __align__(256) __half g_vh[B_ * T_ * NKV * D_];   // fp16 V [B,T,KV,D]
__device__ __align__(256) __half g_yh[B_ * T_ * NH * D_];    // fp16 attention out
__device__ __align__(256) __half g_xh [B_ * T_ * C_];        // fp16 GEMM inputs
__device__ __align__(256) __half g_wqh[NH * D_ * C_];
__device__ __align__(256) __half g_wkh[NKV * D_ * C_];
__device__ __align__(256) __half g_wvh[NKV * D_ * C_];
__device__ __align__(256) __half g_woh[C_ * C_];

// ---------------------------------------------------------------------------
// Helpers (arch-agnostic PTX only — GPU-side build targets plain sm_103,
// which rejects all sm_103a-only features like tcgen05)
// ---------------------------------------------------------------------------
__device__ __forceinline__ uint32_t smem_u32(const void* p) {
    uint32_t a;
    asm("{ .reg .u64 t; cvta.to.shared.u64 t, %1; cvt.u32.u64 %0, t; }"
        : "=r"(a) : "l"(p));
    return a;
}

__device__ __forceinline__ void cp16(uint32_t dst, const void* src) {
    asm volatile("cp.async.cg.shared.global [%0], [%1], 16;\n"
                 :: "r"(dst), "l"(src));
}
#define CP_COMMIT() asm volatile("cp.async.commit_group;" ::: "memory")
#define CP_WAIT1()  asm volatile("cp.async.wait_group 1;" ::: "memory")
#define CP_WAIT0()  asm volatile("cp.async.wait_group 0;" ::: "memory")

// fp16 mma, fp32 accumulate: D[16x8] += A[16x16] * B[16x8]
__device__ __forceinline__ void mma_f16(float* c, const uint32_t* a, const uint32_t* b) {
    asm volatile(
        "mma.sync.aligned.m16n8k16.row.col.f32.f16.f16.f32 "
        "{%0,%1,%2,%3}, {%4,%5,%6,%7}, {%8,%9}, {%0,%1,%2,%3};\n"
        : "+f"(c[0]), "+f"(c[1]), "+f"(c[2]), "+f"(c[3])
        : "r"(a[0]), "r"(a[1]), "r"(a[2]), "r"(a[3]),
          "r"(b[0]), "r"(b[1]));
}

__device__ __forceinline__ void ldsm_x4(uint32_t& r0, uint32_t& r1,
                                        uint32_t& r2, uint32_t& r3, uint32_t addr) {
    asm volatile("ldmatrix.sync.aligned.m8n8.x4.shared.b16 {%0,%1,%2,%3}, [%4];"
                 : "=r"(r0), "=r"(r1), "=r"(r2), "=r"(r3) : "r"(addr));
}

__device__ __forceinline__ void ldsm_x4_t(uint32_t& r0, uint32_t& r1,
                                          uint32_t& r2, uint32_t& r3, uint32_t addr) {
    asm volatile("ldmatrix.sync.aligned.m8n8.x4.trans.shared.b16 {%0,%1,%2,%3}, [%4];"
                 : "=r"(r0), "=r"(r1), "=r"(r2), "=r"(r3) : "r"(addr));
}

__device__ __forceinline__ uint32_t h2u(__half2 h) {
    return *reinterpret_cast<uint32_t*>(&h);
}

__device__ __forceinline__ float ex2(float x) {
    float r;
    asm("ex2.approx.f32 %0, %1;" : "=f"(r) : "f"(x));
    return r;
}

// ---------------------------------------------------------------------------
// fp16 GEMM with fused epilogue.
// C[M,N] = Ah[M,K] * Bh[N,K]^T (fp16 in, fp32 accum).
// MODE 0: fp32 out. MODE 1: RoPE + fp16 out (Q,K). MODE 2: fp16 out (V).
// Block 128x256, k-tile 64 halves, 8 warps (2Mx4N), warp 64x64,
// fragment loads via ldmatrix.x4, cp.async double-buffered.
// ---------------------------------------------------------------------------
#define HST 72
#define A_STAGE_B (128 * HST * 2)           // 18432
#define B_STAGE_B (256 * HST * 2)           // 36864
#define GM_SMEM   (2 * (A_STAGE_B + B_STAGE_B))  // 110592

template <int MODE>
__global__ __launch_bounds__(256, 1) void gemm_h(
    const __half* __restrict__ A, const __half* __restrict__ Bw,
    void* __restrict__ Cv, const float* __restrict__ rope, int M, int N, int K)
{
    extern __shared__ __align__(128) char smem[];
    const uint32_t sbase = smem_u32(smem);
    const uint32_t aoff[2] = { 0u, (uint32_t)A_STAGE_B };
    const uint32_t boff[2] = { 2u * A_STAGE_B, 2u * A_STAGE_B + B_STAGE_B };

    const int tid  = threadIdx.x;
    const int lane = tid & 31;
    const int warp = tid >> 5;
    const int g    = lane >> 2;
    const int tg   = lane & 3;
    const int wm   = warp & 1;
    const int wn   = warp >> 1;
    const int bm   = blockIdx.y << 7;
    const int bn   = blockIdx.x << 8;

    const int arow = tid >> 3;          // 0..31
    const int aseg = tid & 7;           // 16B segs (8 per 128B row)

    // ldmatrix lane offsets (byte units)
    const uint32_t a_lrow = (lane & 7) + (((lane >> 3) & 1) << 3);
    const uint32_t a_kofb = (lane >> 4) << 4;
    const uint32_t b_lrow = (lane & 7) + ((lane >> 4) << 3);
    const uint32_t b_kofb = ((lane >> 3) & 1) << 4;

    float acc[4][8][4];
#pragma unroll
    for (int i = 0; i < 4; i++)
#pragma unroll
        for (int j = 0; j < 8; j++)
#pragma unroll
            for (int e = 0; e < 4; e++) acc[i][j][e] = 0.f;

    const __half* Ag = A  + (size_t)bm * K;
    const __half* Bg = Bw + (size_t)bn * K;

    auto load_stage = [&](int sp, int kt) {
        const __half* As = Ag + (kt << 6);
        const __half* Bs = Bg + (kt << 6);
        const uint32_t ab = sbase + aoff[sp];
        const uint32_t bb = sbase + boff[sp];
#pragma unroll
        for (int i = 0; i < 4; i++) {
            int row = arow + (i << 5);
            cp16(ab + row * (HST * 2) + (aseg << 4), As + (size_t)row * K + (aseg << 3));
        }
#pragma unroll
        for (int i = 0; i < 8; i++) {
            int row = arow + (i << 5);
            cp16(bb + row * (HST * 2) + (aseg << 4), Bs + (size_t)row * K + (aseg << 3));
        }
    };

    const int nkt = K >> 6;   // 32 for K=2048
    load_stage(0, 0); CP_COMMIT();
    load_stage(1, 1); CP_COMMIT();

    for (int kt = 0; kt < nkt; kt++) {
        CP_WAIT1();
        __syncthreads();
        const int s = kt & 1;
        const uint32_t Asm = sbase + aoff[s];
        const uint32_t Bsm = sbase + boff[s];

#pragma unroll
        for (int ks = 0; ks < 4; ks++) {
            uint32_t af[4][4];
            uint32_t bf[8][2];
#pragma unroll
            for (int mt = 0; mt < 4; mt++) {
                const uint32_t addr = Asm +
                    ((wm << 6) + (mt << 4) + a_lrow) * (HST * 2) + (ks << 5) + a_kofb;
                ldsm_x4(af[mt][0], af[mt][1], af[mt][2], af[mt][3], addr);
            }
#pragma unroll
            for (int ntp = 0; ntp < 4; ntp++) {
                const uint32_t addr = Bsm +
                    ((wn << 6) + (ntp << 4) + b_lrow) * (HST * 2) + (ks << 5) + b_kofb;
                ldsm_x4(bf[2 * ntp][0], bf[2 * ntp][1],
                        bf[2 * ntp + 1][0], bf[2 * ntp + 1][1], addr);
            }
#pragma unroll
            for (int mt = 0; mt < 4; mt++)
#pragma unroll
                for (int nt = 0; nt < 8; nt++)
                    mma_f16(acc[mt][nt], af[mt], bf[nt]);
        }
        __syncthreads();
        if (kt + 2 < nkt) load_stage(s, kt + 2);
        CP_COMMIT();
    }

#pragma unroll
    for (int mt = 0; mt < 4; mt++) {
#pragma unroll
        for (int nt = 0; nt < 8; nt++) {
            float v0 = acc[mt][nt][0], v1 = acc[mt][nt][1];
            float v2 = acc[mt][nt][2], v3 = acc[mt][nt][3];
            const int row = bm + (wm << 6) + (mt << 4) + g;
            const int col = bn + (wn << 6) + (nt << 3) + (tg << 1);
            if (MODE == 1) {
                const int t = row & (T_ - 1);
                const int d = col & 127;
                float2 cs0 = *(const float2*)(rope + (size_t)t * 128 + d);
                float2 cs8 = *(const float2*)(rope + (size_t)(t + 8) * 128 + d);
                float o0 = v0 * cs0.x - v1 * cs0.y;
                float o1 = v0 * cs0.y + v1 * cs0.x;
                float o2 = v2 * cs8.x - v3 * cs8.y;
                float o3 = v2 * cs8.y + v3 * cs8.x;
                v0 = o0; v1 = o1; v2 = o2; v3 = o3;
            }
            if (MODE == 0) {
                float* C = (float*)Cv;
                *(float2*)(C + (size_t)row * N + col) = make_float2(v0, v1);
                *(float2*)(C + (size_t)(row + 8) * N + col) = make_float2(v2, v3);
            } else {
                __half* C = (__half*)Cv;
                *(__half2*)(C + (size_t)row * N + col) = __floats2half2_rn(v0, v1);
                *(__half2*)(C + (size_t)(row + 8) * N + col) = __floats2half2_rn(v2, v3);
            }
        }
    }
}

// ---------------------------------------------------------------------------
// fp32 -> fp16 conversion (RNE)
// ---------------------------------------------------------------------------
__global__ void cvt_f2h(__half* __restrict__ dst, const float* __restrict__ src, int n4)
{
    int i = blockIdx.x * blockDim.x + threadIdx.x;
    if (i >= n4) return;
    float4 v = ((const float4*)src)[i];
    __half2* d = (__half2*)dst + 2 * i;
    d[0] = __floats2half2_rn(v.x, v.y);
    d[1] = __floats2half2_rn(v.z, v.w);
}

// All four weight matrices in one launch (segments in float4 units).
__global__ void cvt_w4(__half* dq, __half* dk, __half* dv, __half* dw,
                       const float* sq, const float* sk,
                       const float* sv, const float* sw)
{
    const int n_q  = (NH  * D_ * C_) / 4;   // 1048576
    const int n_kv = (NKV * D_ * C_) / 4;   // 262144
    const int n_o  = (C_ * C_) / 4;         // 1048576
    int i = blockIdx.x * blockDim.x + threadIdx.x;
    const float* src; __half* dst;
    if (i < n_q)                   { src = sq; dst = dq; }
    else if (i < n_q + n_kv)       { src = sk; dst = dk; i -= n_q; }
    else if (i < n_q + 2 * n_kv)   { src = sv; dst = dv; i -= n_q + n_kv; }
    else if (i < n_q + 2 * n_kv + n_o) { src = sw; dst = dw; i -= n_q + 2 * n_kv; }
    else return;
    float4 v = ((const float4*)src)[i];
    __half2* d = (__half2*)dst + 2 * i;
    d[0] = __floats2half2_rn(v.x, v.y);
    d[1] = __floats2half2_rn(v.z, v.w);
}

// ---------------------------------------------------------------------------
// fp16 tensor-core sliding-window attention (window 256), GQA 16:4.
// Block = 4 warps / 64 queries; 3 blocks per SM (12 warps) so softmax
// phases of one block hide under HMMA of another. 10 key-tiles per block.
// QK: K B-frags via ldmatrix.x4, Q frags register-resident.
// P register-direct into PV A-fragments. PV B-frags via ldmatrix.x4.trans.
// ---------------------------------------------------------------------------
#define AKST 136
#define AT_KB (32 * AKST * 2)            // 8704
#define AT_STAGE (2 * AT_KB)             // 17408
#define AT_SMEM  (2 * AT_STAGE)          // 34816

__global__ __launch_bounds__(128, 3) void attn_h(
    const __half* __restrict__ Qh, const __half* __restrict__ Kh,
    const __half* __restrict__ Vh, __half* __restrict__ Y)
{
    extern __shared__ __align__(128) char smem[];
    const uint32_t sb = smem_u32(smem);

    const int tid  = threadIdx.x;
    const int lane = tid & 31;
    const int w    = tid >> 5;          // 0..3
    const int g    = lane >> 2;
    const int tg   = lane & 3;
    const int b    = blockIdx.z;
    const int h    = blockIdx.y;
    const int c0   = blockIdx.x << 6;   // 64 queries per block
    const int kvh  = h >> 2;
    const int tr   = c0 + (w << 4) + g;

    // exp2 scale: log2(e)/sqrt(128)
    const float EXPSCALE = 0.1275174325f;

    // ldmatrix lane offsets (bytes)
    const uint32_t qk_lbase = (lane & 7) * (AKST * 2) + ((lane >> 3) << 4);
    const uint32_t pv_lbase = ((((lane >> 3) & 1) << 3) + (lane & 7)) * (AKST * 2)
                              + ((lane >> 4) << 4);

    // Q fragments: 8 k16 steps, 4 regs each — raw fp16 loads
    uint32_t qf[8][4];
    {
        const __half* q0 = Qh + ((size_t)(b * T_ + tr) * NH + h) * D_;
        const __half* q8 = q0 + (size_t)8 * NH * D_;
#pragma unroll
        for (int ks = 0; ks < 8; ks++) {
            const int c = ks * 16 + (tg << 1);
            qf[ks][0] = *(const uint32_t*)(q0 + c);
            qf[ks][1] = *(const uint32_t*)(q8 + c);
            qf[ks][2] = *(const uint32_t*)(q0 + c + 8);
            qf[ks][3] = *(const uint32_t*)(q8 + c + 8);
        }
    }

    float o[16][4];
#pragma unroll
    for (int i = 0; i < 16; i++)
#pragma unroll
        for (int e = 0; e < 4; e++) o[i][e] = 0.f;
    float l0 = 0.f, l1 = 0.f;

    auto load_tile = [&](int stage, int kbase) {
        const uint32_t kd = sb + stage * AT_STAGE;
        const uint32_t vd = kd + AT_KB;
#pragma unroll
        for (int i = 0; i < 4; i++) {
            int idx = tid + (i << 7);           // 0..511
            int row = idx >> 4, seg = idx & 15;
            const size_t gofs =
                ((size_t)(b * T_ + kbase + row) * NKV + kvh) * D_ + (seg << 3);
            cp16(kd + row * (AKST * 2) + (seg << 4), Kh + gofs);
            cp16(vd + row * (AKST * 2) + (seg << 4), Vh + gofs);
        }
    };

    // Tiles 0..9 cover keys [c0-256, c0+64)
    const int tstart = (c0 >= 256) ? 0 : ((256 - c0) >> 5);
    load_tile(tstart & 1, c0 - 256 + (tstart << 5));
    CP_COMMIT();

    const int wq0 = c0 + (w << 4);

    for (int t = tstart; t < 10; t++) {
        const int kbase = c0 - 256 + (t << 5);
        const int s = t & 1;
        if (t + 1 < 10) {
            load_tile((t + 1) & 1, kbase + 32);
            CP_COMMIT();
            CP_WAIT1();
        } else {
            CP_WAIT0();
        }
        __syncthreads();

        const bool active = !(kbase > wq0 + 15 || kbase + 31 < wq0 - 255);
        if (active) {
            const uint32_t Ksm = sb + s * AT_STAGE;
            const uint32_t Vsm = Ksm + AT_KB;

            // S[16 x 32]
            float sc[4][4];
#pragma unroll
            for (int nc = 0; nc < 4; nc++)
#pragma unroll
                for (int e = 0; e < 4; e++) sc[nc][e] = 0.f;

#pragma unroll
            for (int ksp = 0; ksp < 4; ksp++) {
#pragma unroll
                for (int nc = 0; nc < 4; nc++) {
                    uint32_t r0, r1, r2, r3;
                    const uint32_t addr = Ksm + nc * (8 * AKST * 2) + (ksp << 6) + qk_lbase;
                    ldsm_x4(r0, r1, r2, r3, addr);
                    uint32_t blo[2] = { r0, r1 };
                    uint32_t bhi[2] = { r2, r3 };
                    mma_f16(sc[nc], qf[2 * ksp],     blo);
                    mma_f16(sc[nc], qf[2 * ksp + 1], bhi);
                }
            }

            // mask + exp; P -> PV A-fragments (registers only)
            uint32_t pa[2][4];
#pragma unroll
            for (int nc = 0; nc < 4; nc++) {
                const int col = kbase + nc * 8 + (tg << 1);
                float p0 = ((unsigned)(tr - col)     < 256u) ? ex2(sc[nc][0] * EXPSCALE) : 0.f;
                float p1 = ((unsigned)(tr - col - 1) < 256u) ? ex2(sc[nc][1] * EXPSCALE) : 0.f;
                float p2 = ((unsigned)(tr + 8 - col) < 256u) ? ex2(sc[nc][2] * EXPSCALE) : 0.f;
                float p3 = ((unsigned)(tr + 7 - col) < 256u) ? ex2(sc[nc][3] * EXPSCALE) : 0.f;
                l0 += p0 + p1;
                l1 += p2 + p3;
                const int kc = nc >> 1;       // PV k-step (16 keys each)
                const int hi = nc & 1;        // low/high key octet within k16
                pa[kc][2 * hi]     = h2u(__floats2half2_rn(p0, p1));  // row g
                pa[kc][2 * hi + 1] = h2u(__floats2half2_rn(p2, p3));  // row g+8
            }

            // O += P @ V  (V smem [key][d], trans-ldmatrix -> B frags)
#pragma unroll
            for (int kc = 0; kc < 2; kc++) {
#pragma unroll
                for (int ncp = 0; ncp < 8; ncp++) {
                    uint32_t r0, r1, r2, r3;
                    const uint32_t addr = Vsm + kc * (16 * AKST * 2) + (ncp << 5) + pv_lbase;
                    ldsm_x4_t(r0, r1, r2, r3, addr);
                    uint32_t blo[2] = { r0, r1 };
                    uint32_t bhi[2] = { r2, r3 };
                    mma_f16(o[2 * ncp],     pa[kc], blo);
                    mma_f16(o[2 * ncp + 1], pa[kc], bhi);
                }
            }
        }
        __syncthreads();
    }

    // row-sum across tg lanes
    l0 += __shfl_xor_sync(0xffffffffu, l0, 1);
    l0 += __shfl_xor_sync(0xffffffffu, l0, 2);
    l1 += __shfl_xor_sync(0xffffffffu, l1, 1);
    l1 += __shfl_xor_sync(0xffffffffu, l1, 2);
    const float rl0 = 1.0f / l0;
    const float rl1 = 1.0f / l1;

    __half2* y0 = (__half2*)(Y + ((size_t)(b * T_ + tr) * NH + h) * D_);
    __half2* y8 = (__half2*)(Y + ((size_t)(b * T_ + tr + 8) * NH + h) * D_);
#pragma unroll
    for (int nc = 0; nc < 16; nc++) {
        const int dw = nc * 4 + tg;   // half2 index within 128-d row
        y0[dw] = __floats2half2_rn(o[nc][0] * rl0, o[nc][1] * rl0);
        y8[dw] = __floats2half2_rn(o[nc][2] * rl1, o[nc][3] * rl1);
    }
}

// ---------------------------------------------------------------------------
// Launch. Inputs (metadata order): x, wq, wk, wv, wo, rope_cache. Out: fp32.
// ---------------------------------------------------------------------------
extern "C" void kernel_launch(void* const* d_in, const int* in_sizes, int n_in,
                              void* d_out, int out_size)
{
    const float* x    = (const float*)d_in[0];
    const float* wq   = (const float*)d_in[1];
    const float* wk   = (const float*)d_in[2];
    const float* wv   = (const float*)d_in[3];
    const float* wo   = (const float*)d_in[4];
    const float* rope = (const float*)d_in[5];
    float* out = (float*)d_out;

    __half *pqh, *pkh, *pvh, *pyh, *pxh, *pwqh, *pwkh, *pwvh, *pwoh;
    cudaGetSymbolAddress((void**)&pqh,  g_qh);
    cudaGetSymbolAddress((void**)&pkh,  g_kh);
    cudaGetSymbolAddress((void**)&pvh,  g_vh);
    cudaGetSymbolAddress((void**)&pyh,  g_yh);
    cudaGetSymbolAddress((void**)&pxh,  g_xh);
    cudaGetSymbolAddress((void**)&pwqh, g_wqh);
    cudaGetSymbolAddress((void**)&pwkh, g_wkh);
    cudaGetSymbolAddress((void**)&pwvh, g_wvh);
    cudaGetSymbolAddress((void**)&pwoh, g_woh);

    cudaFuncSetAttribute(gemm_h<0>, cudaFuncAttributeMaxDynamicSharedMemorySize, GM_SMEM);
    cudaFuncSetAttribute(gemm_h<1>, cudaFuncAttributeMaxDynamicSharedMemorySize, GM_SMEM);
    cudaFuncSetAttribute(gemm_h<2>, cudaFuncAttributeMaxDynamicSharedMemorySize, GM_SMEM);
    cudaFuncSetAttribute(attn_h,    cudaFuncAttributeMaxDynamicSharedMemorySize, AT_SMEM);

    const int M = B_ * T_;  // 8192

    // x conversion + all-weights conversion (2 launches)
    {
        int n4 = (B_ * T_ * C_) / 4;
        cvt_f2h<<<(n4 + 255) / 256, 256>>>(pxh, x, n4);
        int nw4 = (NH * D_ * C_ + 2 * NKV * D_ * C_ + C_ * C_) / 4;
        cvt_w4<<<(nw4 + 255) / 256, 256>>>(pwqh, pwkh, pwvh, pwoh, wq, wk, wv, wo);
    }

    // QKV projections with fused epilogues (rope+fp16 for Q/K, fp16 for V)
    gemm_h<1><<<dim3((NH  * D_) / 256, M / 128), 256, GM_SMEM>>>(
        pxh, pwqh, pqh, rope, M, NH * D_, C_);
    gemm_h<1><<<dim3((NKV * D_) / 256, M / 128), 256, GM_SMEM>>>(
        pxh, pwkh, pkh, rope, M, NKV * D_, C_);
    gemm_h<2><<<dim3((NKV * D_) / 256, M / 128), 256, GM_SMEM>>>(
        pxh, pwvh, pvh, nullptr, M, NKV * D_, C_);

    // fp16 tensor-core sliding-window attention -> yh (fp16)
    attn_h<<<dim3(T_ / 64, NH, B_), 128, AT_SMEM>>>(pqh, pkh, pvh, pyh);

    // Output projection (fp16 in, fp32 out)
    gemm_h<0><<<dim3(C_ / 256, M / 128), 256, GM_SMEM>>>(
        pyh, pwoh, out, nullptr, M, C_, C_);
}

// round 9
// speedup vs baseline: 3.5601x; 1.1750x over previous
#include <cuda_runtime.h>
#include <cuda_fp16.h>
#include <cstdint>
#include <cstddef>

#define B_  2
#define T_  4096
#define C_  2048
#define NH  16
#define NKV 4
#define D_  128

// Scratch (allocation-free rule: __device__ globals)
__device__ __align__(256) __half g_qh[B_ * T_ * NH * D_];    // rope'd fp16 Q
__device__ __align__(256) __half g_kh[B_ * T_ * NKV * D_];   // rope'd fp16 K
__device__ __align__(256) __half g_vh[B_ * T_ * NKV * D_];   // fp16 V [B,T,KV,D]
__device__ __align__(256) __half g_yh[B_ * T_ * NH * D_];    // fp16 attention out
__device__ __align__(256) __half g_xh [B_ * T_ * C_];        // fp16 GEMM inputs
__device__ __align__(256) __half g_wqh[NH * D_ * C_];
__device__ __align__(256) __half g_wkh[NKV * D_ * C_];
__device__ __align__(256) __half g_wvh[NKV * D_ * C_];
__device__ __align__(256) __half g_woh[C_ * C_];

// ---------------------------------------------------------------------------
// Helpers (arch-agnostic PTX only — GPU-side build targets plain sm_103,
// which rejects all sm_103a-only features like tcgen05)
// ---------------------------------------------------------------------------
__device__ __forceinline__ uint32_t smem_u32(const void* p) {
    uint32_t a;
    asm("{ .reg .u64 t; cvta.to.shared.u64 t, %1; cvt.u32.u64 %0, t; }"
        : "=r"(a) : "l"(p));
    return a;
}

__device__ __forceinline__ void cp16(uint32_t dst, const void* src) {
    asm volatile("cp.async.cg.shared.global [%0], [%1], 16;\n"
                 :: "r"(dst), "l"(src));
}
#define CP_COMMIT() asm volatile("cp.async.commit_group;" ::: "memory")
#define CP_WAIT1()  asm volatile("cp.async.wait_group 1;" ::: "memory")
#define CP_WAIT0()  asm volatile("cp.async.wait_group 0;" ::: "memory")

// fp16 mma, fp32 accumulate: D[16x8] += A[16x16] * B[16x8]
__device__ __forceinline__ void mma_f16(float* c, const uint32_t* a, const uint32_t* b) {
    asm volatile(
        "mma.sync.aligned.m16n8k16.row.col.f32.f16.f16.f32 "
        "{%0,%1,%2,%3}, {%4,%5,%6,%7}, {%8,%9}, {%0,%1,%2,%3};\n"
        : "+f"(c[0]), "+f"(c[1]), "+f"(c[2]), "+f"(c[3])
        : "r"(a[0]), "r"(a[1]), "r"(a[2]), "r"(a[3]),
          "r"(b[0]), "r"(b[1]));
}

__device__ __forceinline__ void ldsm_x4(uint32_t& r0, uint32_t& r1,
                                        uint32_t& r2, uint32_t& r3, uint32_t addr) {
    asm volatile("ldmatrix.sync.aligned.m8n8.x4.shared.b16 {%0,%1,%2,%3}, [%4];"
                 : "=r"(r0), "=r"(r1), "=r"(r2), "=r"(r3) : "r"(addr));
}

__device__ __forceinline__ void ldsm_x4_t(uint32_t& r0, uint32_t& r1,
                                          uint32_t& r2, uint32_t& r3, uint32_t addr) {
    asm volatile("ldmatrix.sync.aligned.m8n8.x4.trans.shared.b16 {%0,%1,%2,%3}, [%4];"
                 : "=r"(r0), "=r"(r1), "=r"(r2), "=r"(r3) : "r"(addr));
}

__device__ __forceinline__ uint32_t h2u(__half2 h) {
    return *reinterpret_cast<uint32_t*>(&h);
}

__device__ __forceinline__ float ex2(float x) {
    float r;
    asm("ex2.approx.f32 %0, %1;" : "=f"(r) : "f"(x));
    return r;
}

// ---------------------------------------------------------------------------
// fp16 GEMM with fused epilogue — occupancy-2 version.
// C[M,N] = Ah[M,K] * Bh[N,K]^T (fp16 in, fp32 accum).
// MODE 0: fp32 out. MODE 1: RoPE + fp16 out (Q,K). MODE 2: fp16 out (V).
// Block 128x128, k-tile 64 halves, 8 warps (2Mx4N), warp 64x32 ->
// 64-float accumulator -> 2 blocks/SM; one block's HMMA hides the other's
// barriers/loads. Fragment loads via ldmatrix.x4, cp.async double-buffered.
// ---------------------------------------------------------------------------
#define HST 72
#define T_STAGE_B (128 * HST * 2)           // 18432 (A or B tile)
#define GM_SMEM   (4 * T_STAGE_B)           // 73728: 2 stages x (A+B)

template <int MODE>
__global__ __launch_bounds__(256, 2) void gemm_h(
    const __half* __restrict__ A, const __half* __restrict__ Bw,
    void* __restrict__ Cv, const float* __restrict__ rope, int M, int N, int K)
{
    extern __shared__ __align__(128) char smem[];
    const uint32_t sbase = smem_u32(smem);
    const uint32_t aoff[2] = { 0u, 2u * T_STAGE_B };
    const uint32_t boff[2] = { (uint32_t)T_STAGE_B, 3u * T_STAGE_B };

    const int tid  = threadIdx.x;
    const int lane = tid & 31;
    const int warp = tid >> 5;
    const int g    = lane >> 2;
    const int tg   = lane & 3;
    const int wm   = warp & 1;
    const int wn   = warp >> 1;
    const int bm   = blockIdx.y << 7;
    const int bn   = blockIdx.x << 7;

    const int arow = tid >> 3;          // 0..31
    const int aseg = tid & 7;           // 16B segs (8 per 128B row)

    // ldmatrix lane offsets (byte units)
    const uint32_t a_lrow = (lane & 7) + (((lane >> 3) & 1) << 3);
    const uint32_t a_kofb = (lane >> 4) << 4;
    const uint32_t b_lrow = (lane & 7) + ((lane >> 4) << 3);
    const uint32_t b_kofb = ((lane >> 3) & 1) << 4;

    float acc[4][4][4];
#pragma unroll
    for (int i = 0; i < 4; i++)
#pragma unroll
        for (int j = 0; j < 4; j++)
#pragma unroll
            for (int e = 0; e < 4; e++) acc[i][j][e] = 0.f;

    const __half* Ag = A  + (size_t)bm * K;
    const __half* Bg = Bw + (size_t)bn * K;

    auto load_stage = [&](int sp, int kt) {
        const __half* As = Ag + (kt << 6);
        const __half* Bs = Bg + (kt << 6);
        const uint32_t ab = sbase + aoff[sp];
        const uint32_t bb = sbase + boff[sp];
#pragma unroll
        for (int i = 0; i < 4; i++) {
            int row = arow + (i << 5);
            cp16(ab + row * (HST * 2) + (aseg << 4), As + (size_t)row * K + (aseg << 3));
        }
#pragma unroll
        for (int i = 0; i < 4; i++) {
            int row = arow + (i << 5);
            cp16(bb + row * (HST * 2) + (aseg << 4), Bs + (size_t)row * K + (aseg << 3));
        }
    };

    const int nkt = K >> 6;   // 32 for K=2048
    load_stage(0, 0); CP_COMMIT();
    load_stage(1, 1); CP_COMMIT();

    for (int kt = 0; kt < nkt; kt++) {
        CP_WAIT1();
        __syncthreads();
        const int s = kt & 1;
        const uint32_t Asm = sbase + aoff[s];
        const uint32_t Bsm = sbase + boff[s];

#pragma unroll
        for (int ks = 0; ks < 4; ks++) {
            uint32_t af[4][4];
            uint32_t bf[4][2];
#pragma unroll
            for (int mt = 0; mt < 4; mt++) {
                const uint32_t addr = Asm +
                    ((wm << 6) + (mt << 4) + a_lrow) * (HST * 2) + (ks << 5) + a_kofb;
                ldsm_x4(af[mt][0], af[mt][1], af[mt][2], af[mt][3], addr);
            }
#pragma unroll
            for (int ntp = 0; ntp < 2; ntp++) {
                const uint32_t addr = Bsm +
                    ((wn << 5) + (ntp << 4) + b_lrow) * (HST * 2) + (ks << 5) + b_kofb;
                ldsm_x4(bf[2 * ntp][0], bf[2 * ntp][1],
                        bf[2 * ntp + 1][0], bf[2 * ntp + 1][1], addr);
            }
#pragma unroll
            for (int mt = 0; mt < 4; mt++)
#pragma unroll
                for (int nt = 0; nt < 4; nt++)
                    mma_f16(acc[mt][nt], af[mt], bf[nt]);
        }
        __syncthreads();
        if (kt + 2 < nkt) load_stage(s, kt + 2);
        CP_COMMIT();
    }

#pragma unroll
    for (int mt = 0; mt < 4; mt++) {
#pragma unroll
        for (int nt = 0; nt < 4; nt++) {
            float v0 = acc[mt][nt][0], v1 = acc[mt][nt][1];
            float v2 = acc[mt][nt][2], v3 = acc[mt][nt][3];
            const int row = bm + (wm << 6) + (mt << 4) + g;
            const int col = bn + (wn << 5) + (nt << 3) + (tg << 1);
            if (MODE == 1) {
                const int t = row & (T_ - 1);
                const int d = col & 127;
                float2 cs0 = *(const float2*)(rope + (size_t)t * 128 + d);
                float2 cs8 = *(const float2*)(rope + (size_t)(t + 8) * 128 + d);
                float o0 = v0 * cs0.x - v1 * cs0.y;
                float o1 = v0 * cs0.y + v1 * cs0.x;
                float o2 = v2 * cs8.x - v3 * cs8.y;
                float o3 = v2 * cs8.y + v3 * cs8.x;
                v0 = o0; v1 = o1; v2 = o2; v3 = o3;
            }
            if (MODE == 0) {
                float* C = (float*)Cv;
                *(float2*)(C + (size_t)row * N + col) = make_float2(v0, v1);
                *(float2*)(C + (size_t)(row + 8) * N + col) = make_float2(v2, v3);
            } else {
                __half* C = (__half*)Cv;
                *(__half2*)(C + (size_t)row * N + col) = __floats2half2_rn(v0, v1);
                *(__half2*)(C + (size_t)(row + 8) * N + col) = __floats2half2_rn(v2, v3);
            }
        }
    }
}

// ---------------------------------------------------------------------------
// fp32 -> fp16 conversion (RNE)
// ---------------------------------------------------------------------------
__global__ void cvt_f2h(__half* __restrict__ dst, const float* __restrict__ src, int n4)
{
    int i = blockIdx.x * blockDim.x + threadIdx.x;
    if (i >= n4) return;
    float4 v = ((const float4*)src)[i];
    __half2* d = (__half2*)dst + 2 * i;
    d[0] = __floats2half2_rn(v.x, v.y);
    d[1] = __floats2half2_rn(v.z, v.w);
}

// All four weight matrices in one launch (segments in float4 units).
__global__ void cvt_w4(__half* dq, __half* dk, __half* dv, __half* dw,
                       const float* sq, const float* sk,
                       const float* sv, const float* sw)
{
    const int n_q  = (NH  * D_ * C_) / 4;   // 1048576
    const int n_kv = (NKV * D_ * C_) / 4;   // 262144
    const int n_o  = (C_ * C_) / 4;         // 1048576
    int i = blockIdx.x * blockDim.x + threadIdx.x;
    const float* src; __half* dst;
    if (i < n_q)                   { src = sq; dst = dq; }
    else if (i < n_q + n_kv)       { src = sk; dst = dk; i -= n_q; }
    else if (i < n_q + 2 * n_kv)   { src = sv; dst = dv; i -= n_q + n_kv; }
    else if (i < n_q + 2 * n_kv + n_o) { src = sw; dst = dw; i -= n_q + 2 * n_kv; }
    else return;
    float4 v = ((const float4*)src)[i];
    __half2* d = (__half2*)dst + 2 * i;
    d[0] = __floats2half2_rn(v.x, v.y);
    d[1] = __floats2half2_rn(v.z, v.w);
}

// ---------------------------------------------------------------------------
// fp16 tensor-core sliding-window attention (window 256), GQA 16:4.
// Block = 4 warps / 64 queries; 3 blocks per SM. 10 key-tiles per block.
// ---------------------------------------------------------------------------
#define AKST 136
#define AT_KB (32 * AKST * 2)            // 8704
#define AT_STAGE (2 * AT_KB)             // 17408
#define AT_SMEM  (2 * AT_STAGE)          // 34816

__global__ __launch_bounds__(128, 3) void attn_h(
    const __half* __restrict__ Qh, const __half* __restrict__ Kh,
    const __half* __restrict__ Vh, __half* __restrict__ Y)
{
    extern __shared__ __align__(128) char smem[];
    const uint32_t sb = smem_u32(smem);

    const int tid  = threadIdx.x;
    const int lane = tid & 31;
    const int w    = tid >> 5;          // 0..3
    const int g    = lane >> 2;
    const int tg   = lane & 3;
    const int b    = blockIdx.z;
    const int h    = blockIdx.y;
    const int c0   = blockIdx.x << 6;   // 64 queries per block
    const int kvh  = h >> 2;
    const int tr   = c0 + (w << 4) + g;

    const float EXPSCALE = 0.1275174325f;   // log2(e)/sqrt(128)

    const uint32_t qk_lbase = (lane & 7) * (AKST * 2) + ((lane >> 3) << 4);
    const uint32_t pv_lbase = ((((lane >> 3) & 1) << 3) + (lane & 7)) * (AKST * 2)
                              + ((lane >> 4) << 4);

    uint32_t qf[8][4];
    {
        const __half* q0 = Qh + ((size_t)(b * T_ + tr) * NH + h) * D_;
        const __half* q8 = q0 + (size_t)8 * NH * D_;
#pragma unroll
        for (int ks = 0; ks < 8; ks++) {
            const int c = ks * 16 + (tg << 1);
            qf[ks][0] = *(const uint32_t*)(q0 + c);
            qf[ks][1] = *(const uint32_t*)(q8 + c);
            qf[ks][2] = *(const uint32_t*)(q0 + c + 8);
            qf[ks][3] = *(const uint32_t*)(q8 + c + 8);
        }
    }

    float o[16][4];
#pragma unroll
    for (int i = 0; i < 16; i++)
#pragma unroll
        for (int e = 0; e < 4; e++) o[i][e] = 0.f;
    float l0 = 0.f, l1 = 0.f;

    auto load_tile = [&](int stage, int kbase) {
        const uint32_t kd = sb + stage * AT_STAGE;
        const uint32_t vd = kd + AT_KB;
#pragma unroll
        for (int i = 0; i < 4; i++) {
            int idx = tid + (i << 7);           // 0..511
            int row = idx >> 4, seg = idx & 15;
            const size_t gofs =
                ((size_t)(b * T_ + kbase + row) * NKV + kvh) * D_ + (seg << 3);
            cp16(kd + row * (AKST * 2) + (seg << 4), Kh + gofs);
            cp16(vd + row * (AKST * 2) + (seg << 4), Vh + gofs);
        }
    };

    const int tstart = (c0 >= 256) ? 0 : ((256 - c0) >> 5);
    load_tile(tstart & 1, c0 - 256 + (tstart << 5));
    CP_COMMIT();

    const int wq0 = c0 + (w << 4);

    for (int t = tstart; t < 10; t++) {
        const int kbase = c0 - 256 + (t << 5);
        const int s = t & 1;
        if (t + 1 < 10) {
            load_tile((t + 1) & 1, kbase + 32);
            CP_COMMIT();
            CP_WAIT1();
        } else {
            CP_WAIT0();
        }
        __syncthreads();

        const bool active = !(kbase > wq0 + 15 || kbase + 31 < wq0 - 255);
        if (active) {
            const uint32_t Ksm = sb + s * AT_STAGE;
            const uint32_t Vsm = Ksm + AT_KB;

            float sc[4][4];
#pragma unroll
            for (int nc = 0; nc < 4; nc++)
#pragma unroll
                for (int e = 0; e < 4; e++) sc[nc][e] = 0.f;

#pragma unroll
            for (int ksp = 0; ksp < 4; ksp++) {
#pragma unroll
                for (int nc = 0; nc < 4; nc++) {
                    uint32_t r0, r1, r2, r3;
                    const uint32_t addr = Ksm + nc * (8 * AKST * 2) + (ksp << 6) + qk_lbase;
                    ldsm_x4(r0, r1, r2, r3, addr);
                    uint32_t blo[2] = { r0, r1 };
                    uint32_t bhi[2] = { r2, r3 };
                    mma_f16(sc[nc], qf[2 * ksp],     blo);
                    mma_f16(sc[nc], qf[2 * ksp + 1], bhi);
                }
            }

            uint32_t pa[2][4];
#pragma unroll
            for (int nc = 0; nc < 4; nc++) {
                const int col = kbase + nc * 8 + (tg << 1);
                float p0 = ((unsigned)(tr - col)     < 256u) ? ex2(sc[nc][0] * EXPSCALE) : 0.f;
                float p1 = ((unsigned)(tr - col - 1) < 256u) ? ex2(sc[nc][1] * EXPSCALE) : 0.f;
                float p2 = ((unsigned)(tr + 8 - col) < 256u) ? ex2(sc[nc][2] * EXPSCALE) : 0.f;
                float p3 = ((unsigned)(tr + 7 - col) < 256u) ? ex2(sc[nc][3] * EXPSCALE) : 0.f;
                l0 += p0 + p1;
                l1 += p2 + p3;
                const int kc = nc >> 1;
                const int hi = nc & 1;
                pa[kc][2 * hi]     = h2u(__floats2half2_rn(p0, p1));  // row g
                pa[kc][2 * hi + 1] = h2u(__floats2half2_rn(p2, p3));  // row g+8
            }

#pragma unroll
            for (int kc = 0; kc < 2; kc++) {
#pragma unroll
                for (int ncp = 0; ncp < 8; ncp++) {
                    uint32_t r0, r1, r2, r3;
                    const uint32_t addr = Vsm + kc * (16 * AKST * 2) + (ncp << 5) + pv_lbase;
                    ldsm_x4_t(r0, r1, r2, r3, addr);
                    uint32_t blo[2] = { r0, r1 };
                    uint32_t bhi[2] = { r2, r3 };
                    mma_f16(o[2 * ncp],     pa[kc], blo);
                    mma_f16(o[2 * ncp + 1], pa[kc], bhi);
                }
            }
        }
        __syncthreads();
    }

    l0 += __shfl_xor_sync(0xffffffffu, l0, 1);
    l0 += __shfl_xor_sync(0xffffffffu, l0, 2);
    l1 += __shfl_xor_sync(0xffffffffu, l1, 1);
    l1 += __shfl_xor_sync(0xffffffffu, l1, 2);
    const float rl0 = 1.0f / l0;
    const float rl1 = 1.0f / l1;

    __half2* y0 = (__half2*)(Y + ((size_t)(b * T_ + tr) * NH + h) * D_);
    __half2* y8 = (__half2*)(Y + ((size_t)(b * T_ + tr + 8) * NH + h) * D_);
#pragma unroll
    for (int nc = 0; nc < 16; nc++) {
        const int dw = nc * 4 + tg;
        y0[dw] = __floats2half2_rn(o[nc][0] * rl0, o[nc][1] * rl0);
        y8[dw] = __floats2half2_rn(o[nc][2] * rl1, o[nc][3] * rl1);
    }
}

// ---------------------------------------------------------------------------
// Launch. Inputs (metadata order): x, wq, wk, wv, wo, rope_cache. Out: fp32.
// ---------------------------------------------------------------------------
extern "C" void kernel_launch(void* const* d_in, const int* in_sizes, int n_in,
                              void* d_out, int out_size)
{
    const float* x    = (const float*)d_in[0];
    const float* wq   = (const float*)d_in[1];
    const float* wk   = (const float*)d_in[2];
    const float* wv   = (const float*)d_in[3];
    const float* wo   = (const float*)d_in[4];
    const float* rope = (const float*)d_in[5];
    float* out = (float*)d_out;

    __half *pqh, *pkh, *pvh, *pyh, *pxh, *pwqh, *pwkh, *pwvh, *pwoh;
    cudaGetSymbolAddress((void**)&pqh,  g_qh);
    cudaGetSymbolAddress((void**)&pkh,  g_kh);
    cudaGetSymbolAddress((void**)&pvh,  g_vh);
    cudaGetSymbolAddress((void**)&pyh,  g_yh);
    cudaGetSymbolAddress((void**)&pxh,  g_xh);
    cudaGetSymbolAddress((void**)&pwqh, g_wqh);
    cudaGetSymbolAddress((void**)&pwkh, g_wkh);
    cudaGetSymbolAddress((void**)&pwvh, g_wvh);
    cudaGetSymbolAddress((void**)&pwoh, g_woh);

    cudaFuncSetAttribute(gemm_h<0>, cudaFuncAttributeMaxDynamicSharedMemorySize, GM_SMEM);
    cudaFuncSetAttribute(gemm_h<1>, cudaFuncAttributeMaxDynamicSharedMemorySize, GM_SMEM);
    cudaFuncSetAttribute(gemm_h<2>, cudaFuncAttributeMaxDynamicSharedMemorySize, GM_SMEM);
    cudaFuncSetAttribute(attn_h,    cudaFuncAttributeMaxDynamicSharedMemorySize, AT_SMEM);

    const int M = B_ * T_;  // 8192

    {
        int n4 = (B_ * T_ * C_) / 4;
        cvt_f2h<<<(n4 + 255) / 256, 256>>>(pxh, x, n4);
        int nw4 = (NH * D_ * C_ + 2 * NKV * D_ * C_ + C_ * C_) / 4;
        cvt_w4<<<(nw4 + 255) / 256, 256>>>(pwqh, pwkh, pwvh, pwoh, wq, wk, wv, wo);
    }

    // QKV projections with fused epilogues (rope+fp16 for Q/K, fp16 for V)
    gemm_h<1><<<dim3((NH  * D_) / 128, M / 128), 256, GM_SMEM>>>(
        pxh, pwqh, pqh, rope, M, NH * D_, C_);
    gemm_h<1><<<dim3((NKV * D_) / 128, M / 128), 256, GM_SMEM>>>(
        pxh, pwkh, pkh, rope, M, NKV * D_, C_);
    gemm_h<2><<<dim3((NKV * D_) / 128, M / 128), 256, GM_SMEM>>>(
        pxh, pwvh, pvh, nullptr, M, NKV * D_, C_);

    // fp16 tensor-core sliding-window attention -> yh (fp16)
    attn_h<<<dim3(T_ / 64, NH, B_), 128, AT_SMEM>>>(pqh, pkh, pvh, pyh);

    // Output projection (fp16 in, fp32 out)
    gemm_h<0><<<dim3(C_ / 128, M / 128), 256, GM_SMEM>>>(
        pyh, pwoh, out, nullptr, M, C_, C_);
}